// round 15
// baseline (speedup 1.0000x reference)
#include <cuda_runtime.h>
#include <cuda_fp16.h>
#include <cstdint>
#include <cstddef>
#include <math.h>

#define BB 128
#define NN 4096
#define HALF_N 2048
#define MM 64
#define PR 1584   // stacked: 512 Wk + 512 We + 512 Wa + 24 Ws + 8 Wbeta + 8 Wg + 8 Wgam

// ---------------- scratch (device globals; no allocations) ----------------
__device__ float g_x[BB * 512];
__device__ float g_c[BB * 512];
__device__ float g_hr[BB * 768];           // [h(512) | read0..3 (4*64)]
__device__ float g_Wstk[PR * 512];
__device__ float g_gp[8 * BB * 2048];      // gates GEMM split-K partials
__device__ float g_pp[8 * BB * PR];        // head-param GEMM partials
__device__ float g_op[6 * BB * 256];       // output GEMM partials
__device__ float g_keyv[8 * BB * MM];
__device__ float g_keynorm[8 * BB];
__device__ float g_ev[8 * BB * MM];
__device__ float g_av[8 * BB * MM];
__device__ float g_beta[8 * BB];
__device__ float g_gv[8 * BB];
__device__ float g_gamma[8 * BB];
__device__ float g_sv[8 * BB * 3];
__device__ __half g_memh[(size_t)BB * NN * MM];  // fp16 cache of original memory

__device__ __forceinline__ float sigf(float x) { return 1.f / (1.f + __expf(-x)); }
__device__ __forceinline__ float softplusf(float x) {
    return fmaxf(x, 0.f) + log1pf(expf(-fabsf(x)));
}

// ---------------- cluster helpers ----------------
__device__ __forceinline__ uint32_t s2u(const void* p) {
    uint32_t a;
    asm("{ .reg .u64 t; cvta.to.shared.u64 t, %1; cvt.u32.u64 %0, t; }" : "=r"(a) : "l"(p));
    return a;
}
__device__ __forceinline__ float dsmem_ld(uint32_t local_addr, uint32_t peer) {
    uint32_t r;
    asm("mapa.shared::cluster.u32 %0, %1, %2;" : "=r"(r) : "r"(local_addr), "r"(peer));
    float f;
    asm volatile("ld.shared::cluster.f32 %0, [%1];" : "=f"(f) : "r"(r));
    return f;
}
#define CLUSTER_SYNC() do { \
    asm volatile("barrier.cluster.arrive.aligned;" ::: "memory"); \
    asm volatile("barrier.cluster.wait.aligned;" ::: "memory"); \
} while (0)

// ---------------- combined pack kernel ----------------
__global__ void pack_all_kernel(const float* __restrict__ in_data,
                                const float* __restrict__ prev_reads,
                                const float* __restrict__ Wk, const float* __restrict__ We,
                                const float* __restrict__ Wa, const float* __restrict__ Ws,
                                const float* __restrict__ Wbeta, const float* __restrict__ Wg,
                                const float* __restrict__ Wgam) {
    int idx = blockIdx.x * blockDim.x + threadIdx.x;
    if (idx < BB * 512) {
        int b = idx >> 9, c = idx & 511;
        float v;
        if (c < 256) v = in_data[b * 256 + c];
        else {
            int k = c - 256, i = k >> 6, m = k & 63;
            v = prev_reads[((size_t)i * BB + b) * MM + m];
        }
        g_x[idx] = v;
        return;
    }
    int j = idx - BB * 512;
    if (j >= PR * 512) return;
    int r = j >> 9, k = j & 511;
    float v;
    if (r < 512)        v = Wk[(size_t)r * 512 + k];
    else if (r < 1024)  v = We[(size_t)(r - 512) * 512 + k];
    else if (r < 1536)  v = Wa[(size_t)(r - 1024) * 512 + k];
    else if (r < 1560)  v = Ws[(size_t)(r - 1536) * 512 + k];
    else if (r < 1568)  v = Wbeta[(size_t)(r - 1560) * 512 + k];
    else if (r < 1576)  v = Wg[(size_t)(r - 1568) * 512 + k];
    else                v = Wgam[(size_t)(r - 1576) * 512 + k];
    g_Wstk[j] = v;
}

// ---------------- split-K SGEMM body ----------------
__device__ __forceinline__ void gemm_body(
    const float* __restrict__ A, const float* __restrict__ W,
    float* __restrict__ Cp, int R, int K, int kChunk, int kStart, int slot,
    int mBase, int rBase)
{
    __shared__ __align__(16) float As[16][68];
    __shared__ __align__(16) float Bs[16][68];
    const int t = threadIdx.x;
    const int tx = t & 15, ty = t >> 4;
    const int loadRow = t >> 2;
    const int loadK = (t & 3) * 4;
    const float* Arow = A + (size_t)(mBase + loadRow) * K;
    const bool wv = (rBase + loadRow) < R;
    const float* Wrow = W + (size_t)(wv ? (rBase + loadRow) : 0) * K;
    float acc[4][4] = {};
    for (int k0 = kStart; k0 < kStart + kChunk; k0 += 16) {
        float4 a4 = *reinterpret_cast<const float4*>(Arow + k0 + loadK);
        float4 w4 = *reinterpret_cast<const float4*>(Wrow + k0 + loadK);
        if (!wv) w4 = make_float4(0.f, 0.f, 0.f, 0.f);
        __syncthreads();
        As[loadK + 0][loadRow] = a4.x; As[loadK + 1][loadRow] = a4.y;
        As[loadK + 2][loadRow] = a4.z; As[loadK + 3][loadRow] = a4.w;
        Bs[loadK + 0][loadRow] = w4.x; Bs[loadK + 1][loadRow] = w4.y;
        Bs[loadK + 2][loadRow] = w4.z; Bs[loadK + 3][loadRow] = w4.w;
        __syncthreads();
#pragma unroll
        for (int kk = 0; kk < 16; kk++) {
            float4 av = *reinterpret_cast<const float4*>(&As[kk][ty * 4]);
            float4 wv4 = *reinterpret_cast<const float4*>(&Bs[kk][tx * 4]);
            float aa[4] = {av.x, av.y, av.z, av.w};
            float ww[4] = {wv4.x, wv4.y, wv4.z, wv4.w};
#pragma unroll
            for (int i = 0; i < 4; i++)
#pragma unroll
                for (int j = 0; j < 4; j++)
                    acc[i][j] = fmaf(aa[i], ww[j], acc[i][j]);
        }
    }
#pragma unroll
    for (int i = 0; i < 4; i++) {
        int m = mBase + ty * 4 + i;
#pragma unroll
        for (int j = 0; j < 4; j++) {
            int r = rBase + tx * 4 + j;
            if (r < R) Cp[((size_t)slot * BB + m) * R + r] = acc[i][j];
        }
    }
}

__global__ __launch_bounds__(256) void gemm_tn(
    const float* __restrict__ A, const float* __restrict__ W,
    float* __restrict__ Cp, int R, int K, int kChunk, int slotBase)
{
    gemm_body(A, W, Cp, R, K, kChunk, blockIdx.z * kChunk, slotBase + blockIdx.z,
              blockIdx.y * 64, blockIdx.x * 64);
}

__global__ __launch_bounds__(256) void gemm_gates(
    const float* __restrict__ A0, const float* __restrict__ W0,
    const float* __restrict__ A1, const float* __restrict__ W1,
    float* __restrict__ Cp)
{
    const int z = blockIdx.z;
    const float* A = (z < 4) ? A0 : A1;
    const float* W = (z < 4) ? W0 : W1;
    gemm_body(A, W, Cp, 2048, 512, 128, (z & 3) * 128, z, blockIdx.y * 64, blockIdx.x * 64);
}

// ---------------- LSTM epilogue ----------------
__global__ void lstm_act_kernel(const float* __restrict__ b_ih, const float* __restrict__ b_hh,
                                const float* __restrict__ c_prev) {
    int idx = blockIdx.x * blockDim.x + threadIdx.x;
    if (idx >= BB * 128) return;
    int b = idx >> 7, j4 = (idx & 127) * 4;
    float4 s[4];
#pragma unroll
    for (int q = 0; q < 4; q++) {
        int col = q * 512 + j4;
        float4 bi = *reinterpret_cast<const float4*>(b_ih + col);
        float4 bh = *reinterpret_cast<const float4*>(b_hh + col);
        s[q] = make_float4(bi.x + bh.x, bi.y + bh.y, bi.z + bh.z, bi.w + bh.w);
    }
#pragma unroll
    for (int sl = 0; sl < 8; sl++) {
        const float* base = g_gp + ((size_t)sl * BB + b) * 2048;
#pragma unroll
        for (int q = 0; q < 4; q++) {
            float4 p = *reinterpret_cast<const float4*>(base + q * 512 + j4);
            s[q].x += p.x; s[q].y += p.y; s[q].z += p.z; s[q].w += p.w;
        }
    }
    float4 cp = *reinterpret_cast<const float4*>(c_prev + b * 512 + j4);
    float cc0 = sigf(s[1].x) * cp.x + sigf(s[0].x) * tanhf(s[2].x);
    float cc1 = sigf(s[1].y) * cp.y + sigf(s[0].y) * tanhf(s[2].y);
    float cc2 = sigf(s[1].z) * cp.z + sigf(s[0].z) * tanhf(s[2].z);
    float cc3 = sigf(s[1].w) * cp.w + sigf(s[0].w) * tanhf(s[2].w);
    *reinterpret_cast<float4*>(g_c + b * 512 + j4) = make_float4(cc0, cc1, cc2, cc3);
    float4 hh = make_float4(sigf(s[3].x) * tanhf(cc0), sigf(s[3].y) * tanhf(cc1),
                            sigf(s[3].z) * tanhf(cc2), sigf(s[3].w) * tanhf(cc3));
    *reinterpret_cast<float4*>(g_hr + (size_t)b * 768 + j4) = hh;
}

// ---------------- head-param epilogue ----------------
__global__ __launch_bounds__(256) void param_act_kernel(
    const float* __restrict__ bk, const float* __restrict__ be,
    const float* __restrict__ ba, const float* __restrict__ bs,
    const float* __restrict__ bbeta, const float* __restrict__ bg,
    const float* __restrict__ bgam) {
    const int b = blockIdx.x;
    const int t = threadIdx.x;
    __shared__ float s_np[128];
    __shared__ float s_sh[24];

    for (int f4 = t; f4 < 396; f4 += 256) {
        int r = f4 * 4;
        float4 v = make_float4(0.f, 0.f, 0.f, 0.f);
#pragma unroll
        for (int sl = 0; sl < 8; sl++) {
            float4 p = *reinterpret_cast<const float4*>(
                g_pp + ((size_t)sl * BB + b) * PR + r);
            v.x += p.x; v.y += p.y; v.z += p.z; v.w += p.w;
        }
        if (r < 512) {
            float4 bb4 = *reinterpret_cast<const float4*>(bk + r);
            v.x += bb4.x; v.y += bb4.y; v.z += bb4.z; v.w += bb4.w;
            int head = r >> 6, m = r & 63;
            *reinterpret_cast<float4*>(g_keyv + ((size_t)head * BB + b) * 64 + m) = v;
            s_np[f4] = v.x * v.x + v.y * v.y + v.z * v.z + v.w * v.w;
        } else if (r < 1024) {
            int rr = r - 512;
            float4 bb4 = *reinterpret_cast<const float4*>(be + rr);
            int head = rr >> 6, m = rr & 63;
            float4 o = make_float4(sigf(v.x + bb4.x), sigf(v.y + bb4.y),
                                   sigf(v.z + bb4.z), sigf(v.w + bb4.w));
            *reinterpret_cast<float4*>(g_ev + ((size_t)head * BB + b) * 64 + m) = o;
        } else if (r < 1536) {
            int rr = r - 1024;
            float4 bb4 = *reinterpret_cast<const float4*>(ba + rr);
            int head = rr >> 6, m = rr & 63;
            float4 o = make_float4(tanhf(v.x + bb4.x), tanhf(v.y + bb4.y),
                                   tanhf(v.z + bb4.z), tanhf(v.w + bb4.w));
            *reinterpret_cast<float4*>(g_av + ((size_t)head * BB + b) * 64 + m) = o;
        } else if (r < 1560) {
            int rr = r - 1536;
            s_sh[rr + 0] = v.x + bs[rr + 0];
            s_sh[rr + 1] = v.y + bs[rr + 1];
            s_sh[rr + 2] = v.z + bs[rr + 2];
            s_sh[rr + 3] = v.w + bs[rr + 3];
        } else if (r < 1568) {
            int rr = r - 1560;
            g_beta[(rr + 0) * BB + b] = softplusf(v.x + bbeta[rr + 0]);
            g_beta[(rr + 1) * BB + b] = softplusf(v.y + bbeta[rr + 1]);
            g_beta[(rr + 2) * BB + b] = softplusf(v.z + bbeta[rr + 2]);
            g_beta[(rr + 3) * BB + b] = softplusf(v.w + bbeta[rr + 3]);
        } else if (r < 1576) {
            int rr = r - 1568;
            g_gv[(rr + 0) * BB + b] = sigf(v.x + bg[rr + 0]);
            g_gv[(rr + 1) * BB + b] = sigf(v.y + bg[rr + 1]);
            g_gv[(rr + 2) * BB + b] = sigf(v.z + bg[rr + 2]);
            g_gv[(rr + 3) * BB + b] = sigf(v.w + bg[rr + 3]);
        } else {
            int rr = r - 1576;
            g_gamma[(rr + 0) * BB + b] = 1.f + softplusf(v.x + bgam[rr + 0]);
            g_gamma[(rr + 1) * BB + b] = 1.f + softplusf(v.y + bgam[rr + 1]);
            g_gamma[(rr + 2) * BB + b] = 1.f + softplusf(v.z + bgam[rr + 2]);
            g_gamma[(rr + 3) * BB + b] = 1.f + softplusf(v.w + bgam[rr + 3]);
        }
    }
    __syncthreads();
    if (t < 8) {
        float s = 0.f;
#pragma unroll
        for (int j = 0; j < 16; j++) s += s_np[t * 16 + j];
        g_keynorm[t * BB + b] = sqrtf(s);
        float x0 = s_sh[t * 3], x1 = s_sh[t * 3 + 1], x2 = s_sh[t * 3 + 2];
        float m = fmaxf(x0, fmaxf(x1, x2));
        float e0 = expf(x0 - m), e1 = expf(x1 - m), e2 = expf(x2 - m);
        float d = e0 + e1 + e2;
        size_t hb = (size_t)t * BB + b;
        g_sv[hb * 3 + 0] = e0 / d;
        g_sv[hb * 3 + 1] = e1 / d;
        g_sv[hb * 3 + 2] = e2 / d;
    }
}

// ---------------- mega pass kernel (cluster of 2 CTAs per batch) ----------------
__device__ __forceinline__ float2 blk_reduce_f2(float2 v, float2* red) {
    int lane = threadIdx.x & 31, wid = threadIdx.x >> 5;
#pragma unroll
    for (int off = 16; off >= 1; off >>= 1) {
        v.x += __shfl_xor_sync(0xffffffffu, v.x, off);
        v.y += __shfl_xor_sync(0xffffffffu, v.y, off);
    }
    if (lane == 0) red[wid] = v;
    __syncthreads();
    if (wid == 0) {
        float2 x = (lane < 16) ? red[lane] : make_float2(0.f, 0.f);
#pragma unroll
        for (int off = 8; off >= 1; off >>= 1) {
            x.x += __shfl_xor_sync(0xffffffffu, x.x, off);
            x.y += __shfl_xor_sync(0xffffffffu, x.y, off);
        }
        if (lane == 0) red[0] = x;
    }
    __syncthreads();
    float2 r = red[0];
    __syncthreads();
    return r;
}

__device__ __forceinline__ void upd8(__half2* v, __half2 w2,
                                     const __half2* ne, const __half2* a) {
#pragma unroll
    for (int j = 0; j < 4; j++)
        v[j] = __hfma2(w2, __hfma2(ne[j], v[j], a[j]), v[j]);
}

// smem float-index layout:
// simA 0..2047 | simB 2048..4095 | wg 4096..6143 | red(16 f2) 6144..6175 |
// readp 6176..6239 | bnd 6240..6241 | slotA 6242(f2) | slotB 6244(f2) | pad |
// halves at float idx 6248: whr/wh1/wh3/wh5 2048 halves each (16384 B)
#define MEGA_SMEM (6248 * 4 + 4 * 2048 * 2 + 64)

template <int ST>
__device__ void pass_body(const float* __restrict__ mem,
                          const float* __restrict__ prev_weights,
                          int b, int rank, float* smem)
{
    constexpr bool HAS_READ = (ST >= 1);
    constexpr int RIDX = (ST - 1);
    constexpr bool HAS_POST = (ST >= 1 && ST <= 3);
    constexpr int NSIM = (ST <= 2) ? 2 : (ST == 3) ? 1 : 0;
    constexpr int SH0 = 2 * ST;

    float* s_simA = smem;
    float* s_simB = smem + 2048;
    float* s_wg   = smem + 4096;
    float2* s_red = reinterpret_cast<float2*>(smem + 6144);
    float* s_readp = smem + 6176;
    float* s_bnd  = smem + 6240;
    float2* s_slotA = reinterpret_cast<float2*>(smem + 6242);
    float2* s_slotB = reinterpret_cast<float2*>(smem + 6244);
    __half* s_whr = reinterpret_cast<__half*>(smem + 6248);
    __half* s_wh1 = s_whr + 2048;
    __half* s_wh3 = s_wh1 + 2048;
    __half* s_wh5 = s_wh3 + 2048;

    const int tid = threadIdx.x;
    const int lane = tid & 31;
    const int warpId = tid >> 5;
    const int sub = lane & 7;
    const int rsel = lane >> 3;
    const uint32_t peer = (uint32_t)(rank ^ 1);
    const int nbase = rank * HALF_N;

    auto ldh8 = [&](const float* base, int head, __half2* dst, bool neg) {
        const float* p = base + ((size_t)head * BB + b) * 64 + sub * 8;
        float4 f0 = *reinterpret_cast<const float4*>(p);
        float4 f1 = *reinterpret_cast<const float4*>(p + 4);
        dst[0] = __floats2half2_rn(f0.x, f0.y); dst[1] = __floats2half2_rn(f0.z, f0.w);
        dst[2] = __floats2half2_rn(f1.x, f1.y); dst[3] = __floats2half2_rn(f1.z, f1.w);
        if (neg) {
#pragma unroll
            for (int j = 0; j < 4; j++) dst[j] = __hneg2(dst[j]);
        }
    };

    __half2 ne1[4], a1[4], ne3[4], a3[4], ne5[4], a5[4], k0[4], k1[4];
    float kn0 = 0.f, kn1 = 0.f;
    if (ST >= 1) { ldh8(g_ev, 1, ne1, true); ldh8(g_av, 1, a1, false); }
    if (ST >= 2) { ldh8(g_ev, 3, ne3, true); ldh8(g_av, 3, a3, false); }
    if (ST >= 3) { ldh8(g_ev, 5, ne5, true); ldh8(g_av, 5, a5, false); }
    if (NSIM >= 1) { ldh8(g_keyv, SH0, k0, false); kn0 = g_keynorm[SH0 * BB + b]; }
    if (NSIM >= 2) { ldh8(g_keyv, SH0 + 1, k1, false); kn1 = g_keynorm[(SH0 + 1) * BB + b]; }

    float racc[8] = {};
    __half2 racc2[4] = {__floats2half2_rn(0.f, 0.f), __floats2half2_rn(0.f, 0.f),
                        __floats2half2_rn(0.f, 0.f), __floats2half2_rn(0.f, 0.f)};
    const size_t bn = (size_t)b * NN + nbase;
    const int rowInBlk = warpId * 4 + rsel;  // 0..63

    // ---- phase A over own 2048 rows, software pipelined ----
    uint4 cu = make_uint4(0, 0, 0, 0);
    float4 cf0 = make_float4(0, 0, 0, 0), cf1 = cf0;
    __half cwrh = __float2half_rn(0.f), cw1h = cwrh, cw3h = cwrh, cw5h = cwrh;
    {
        const int ln = rowInBlk;
        const size_t hidx = (bn + ln) * 64 + sub * 8;
        if (ST == 0) {
            cf0 = __ldcs(reinterpret_cast<const float4*>(mem + hidx));
            cf1 = __ldcs(reinterpret_cast<const float4*>(mem + hidx + 4));
        } else {
            cu = __ldg(reinterpret_cast<const uint4*>(g_memh + hidx));
        }
        if (ST >= 1) { cwrh = s_whr[ln]; cw1h = s_wh1[ln]; }
        if (ST >= 2) cw3h = s_wh3[ln];
        if (ST >= 3) cw5h = s_wh5[ln];
    }

#pragma unroll 4
    for (int it = 0; it < 32; it++) {
        const int ln = it * 64 + rowInBlk;
        const int ln2 = (it < 31) ? (ln + 64) : rowInBlk;
        uint4 nu = make_uint4(0, 0, 0, 0);
        float4 nf0 = make_float4(0, 0, 0, 0), nf1 = nf0;
        __half nwrh = __float2half_rn(0.f), nw1h = nwrh, nw3h = nwrh, nw5h = nwrh;
        {
            const size_t hidx2 = (bn + ln2) * 64 + sub * 8;
            if (ST == 0) {
                nf0 = __ldcs(reinterpret_cast<const float4*>(mem + hidx2));
                nf1 = __ldcs(reinterpret_cast<const float4*>(mem + hidx2 + 4));
            } else {
                nu = __ldg(reinterpret_cast<const uint4*>(g_memh + hidx2));
            }
            if (ST >= 1) { nwrh = s_whr[ln2]; nw1h = s_wh1[ln2]; }
            if (ST >= 2) nw3h = s_wh3[ln2];
            if (ST >= 3) nw5h = s_wh5[ln2];
        }
        __half2 v[4];
        if (ST == 0) {
            v[0] = __floats2half2_rn(cf0.x, cf0.y); v[1] = __floats2half2_rn(cf0.z, cf0.w);
            v[2] = __floats2half2_rn(cf1.x, cf1.y); v[3] = __floats2half2_rn(cf1.z, cf1.w);
            const size_t hidx = (bn + ln) * 64 + sub * 8;
            *reinterpret_cast<uint4*>(g_memh + hidx) = *reinterpret_cast<uint4*>(v);
        } else {
            *reinterpret_cast<uint4*>(v) = cu;
        }
        if (ST >= 2) upd8(v, __half2half2(cw1h), ne1, a1);
        if (ST >= 3) upd8(v, __half2half2(cw3h), ne3, a3);
        if (ST == 4) upd8(v, __half2half2(cw5h), ne5, a5);
        if (HAS_READ) {
            __half2 w2r = __half2half2(cwrh);
#pragma unroll
            for (int j = 0; j < 4; j++)
                racc2[j] = __hfma2(w2r, v[j], racc2[j]);
            if ((it & 3) == 3) {
#pragma unroll
                for (int j = 0; j < 4; j++) {
                    float2 f = __half22float2(racc2[j]);
                    racc[2 * j] += f.x; racc[2 * j + 1] += f.y;
                    racc2[j] = __floats2half2_rn(0.f, 0.f);
                }
            }
        }
        if (HAS_POST) {
            __half pwh = (ST == 1) ? cw1h : (ST == 2) ? cw3h : cw5h;
            const __half2* pne = (ST == 1) ? ne1 : (ST == 2) ? ne3 : ne5;
            const __half2* pa  = (ST == 1) ? a1  : (ST == 2) ? a3  : a5;
            upd8(v, __half2half2(pwh), pne, pa);
        }
        if (NSIM >= 1) {
            __half2 ns2 = __floats2half2_rn(0.f, 0.f);
            __half2 d02 = ns2, d12 = ns2;
#pragma unroll
            for (int j = 0; j < 4; j++) {
                ns2 = __hfma2(v[j], v[j], ns2);
                d02 = __hfma2(v[j], k0[j], d02);
                if (NSIM >= 2) d12 = __hfma2(v[j], k1[j], d12);
            }
            float2 nsf = __half22float2(ns2);
            float2 d0f2 = __half22float2(d02);
            float ns = nsf.x + nsf.y;
            float d0 = d0f2.x + d0f2.y;
            float d1 = 0.f;
            if (NSIM >= 2) { float2 t2 = __half22float2(d12); d1 = t2.x + t2.y; }
#pragma unroll
            for (int off = 4; off >= 1; off >>= 1) {
                ns += __shfl_xor_sync(0xffffffffu, ns, off);
                d0 += __shfl_xor_sync(0xffffffffu, d0, off);
                if (NSIM >= 2) d1 += __shfl_xor_sync(0xffffffffu, d1, off);
            }
            if (sub == 0) {
                float nm = sqrtf(ns);
                s_simA[ln] = d0 / (nm * kn0 + 1e-8f);
                if (NSIM >= 2) s_simB[ln] = d1 / (nm * kn1 + 1e-8f);
            }
        }
        cu = nu; cf0 = nf0; cf1 = nf1;
        cwrh = nwrh; cw1h = nw1h; cw3h = nw3h; cw5h = nw5h;
    }

    // ---- read reduction: local 64-partial, then cluster combine (rank 0 writes) ----
    if (HAS_READ) {
        __syncthreads();
#pragma unroll
        for (int j = 0; j < 8; j++) {
            racc[j] += __shfl_down_sync(0xffffffffu, racc[j], 16);
            racc[j] += __shfl_down_sync(0xffffffffu, racc[j], 8);
        }
        if (lane < 8) {
#pragma unroll
            for (int j = 0; j < 8; j++)
                s_wg[warpId * 64 + sub * 8 + j] = racc[j];
        }
        __syncthreads();
        float myp = 0.f;
        if (tid < 64) {
            for (int w = 0; w < 16; w++) myp += s_wg[w * 64 + tid];
            s_readp[tid] = myp;
        }
        CLUSTER_SYNC();
        if (rank == 0 && tid < 64) {
            float pp = dsmem_ld(s2u(s_readp + tid), peer);
            g_hr[(size_t)b * 768 + 512 + RIDX * 64 + tid] = myp + pp;
        }
        CLUSTER_SYNC();
    }
    __syncthreads();

    // ---- phase B: weights for own rows, cluster-combined sums ----
    if (NSIM >= 1) {
        const int hbA = SH0 * BB + b;
        const int hbB = (SH0 + 1) * BB + b;
        __half* destA = s_whr;
        __half* destB = (ST == 0) ? s_wh1 : (ST == 1) ? s_wh3 : s_wh5;
        const float* pwA = prev_weights + (size_t)hbA * NN + nbase;
        const float* pwB = prev_weights + (size_t)hbB * NN + nbase;
        const float betaA = g_beta[hbA], ggA = g_gv[hbA], gamA = g_gamma[hbA];
        const float sA0 = g_sv[(size_t)hbA * 3 + 0];
        const float sA1 = g_sv[(size_t)hbA * 3 + 1];
        const float sA2 = g_sv[(size_t)hbA * 3 + 2];
        float betaB = 0.f, ggB = 0.f, gamB = 1.f, sB0 = 0.f, sB1 = 0.f, sB2 = 0.f;
        if (NSIM >= 2) {
            betaB = g_beta[hbB]; ggB = g_gv[hbB]; gamB = g_gamma[hbB];
            sB0 = g_sv[(size_t)hbB * 3 + 0];
            sB1 = g_sv[(size_t)hbB * 3 + 1];
            sB2 = g_sv[(size_t)hbB * 3 + 2];
        }

        // exp + local sums
        float exA[4], exB[4];
        float2 se = make_float2(0.f, 0.f);
#pragma unroll
        for (int j = 0; j < 4; j++) {
            int n = tid + 512 * j;
            exA[j] = __expf(betaA * s_simA[n]); se.x += exA[j];
            if (NSIM >= 2) { exB[j] = __expf(betaB * s_simB[n]); se.y += exB[j]; }
        }
        se = blk_reduce_f2(se, s_red);
        if (tid == 0) *s_slotA = se;
        CLUSTER_SYNC();
        if (tid == 0) {
            float2 ps;
            ps.x = dsmem_ld(s2u(&s_slotA->x), peer);
            ps.y = dsmem_ld(s2u(&s_slotA->y), peer);
            s_slotB->x = se.x + ps.x;
            s_slotB->y = se.y + ps.y;
        }
        __syncthreads();
        float2 seT = *s_slotB;
        const float invA = 1.f / seT.x;
        const float invB = (NSIM >= 2) ? 1.f / seT.y : 0.f;
#pragma unroll
        for (int j = 0; j < 4; j++) {
            int n = tid + 512 * j;
            s_simA[n] = ggA * (exA[j] * invA) + (1.f - ggA) * pwA[n];
            if (NSIM >= 2) s_simB[n] = ggB * (exB[j] * invB) + (1.f - ggB) * pwB[n];
        }
        __syncthreads();
        // export boundaries for circular shift (peer's first/last)
        if (tid == 0) {
            s_bnd[0] = s_simA[0];
            s_bnd[1] = s_simA[2047];
            if (NSIM >= 2) {
                s_readp[0] = s_simB[0];
                s_readp[1] = s_simB[2047];
            }
        }
        CLUSTER_SYNC();
        float pFirstA = dsmem_ld(s2u(&s_bnd[0]), peer);
        float pLastA  = dsmem_ld(s2u(&s_bnd[1]), peer);
        float pFirstB = 0.f, pLastB = 0.f;
        if (NSIM >= 2) {
            pFirstB = dsmem_ld(s2u(&s_readp[0]), peer);
            pLastB  = dsmem_ld(s2u(&s_readp[1]), peer);
        }
        // shift + sharpen + local sums
        float pA[4], pB[4];
        float2 sp = make_float2(0.f, 0.f);
#pragma unroll
        for (int j = 0; j < 4; j++) {
            int n = tid + 512 * j;
            float nextA = (n < 2047) ? s_simA[n + 1] : pFirstA;
            float prevA = (n > 0) ? s_simA[n - 1] : pLastA;
            float wsA = sA0 * nextA + sA1 * s_simA[n] + sA2 * prevA;
            pA[j] = __powf(wsA, gamA); sp.x += pA[j];
            if (NSIM >= 2) {
                float nextB = (n < 2047) ? s_simB[n + 1] : pFirstB;
                float prevB = (n > 0) ? s_simB[n - 1] : pLastB;
                float wsB = sB0 * nextB + sB1 * s_simB[n] + sB2 * prevB;
                pB[j] = __powf(wsB, gamB); sp.y += pB[j];
            }
        }
        sp = blk_reduce_f2(sp, s_red);
        if (tid == 0) *s_slotA = sp;
        CLUSTER_SYNC();
        if (tid == 0) {
            float2 ps;
            ps.x = dsmem_ld(s2u(&s_slotA->x), peer);
            ps.y = dsmem_ld(s2u(&s_slotA->y), peer);
            s_slotB->x = sp.x + ps.x;
            s_slotB->y = sp.y + ps.y;
        }
        __syncthreads();
        float2 spT = *s_slotB;
        const float invpA = 1.f / (spT.x + 1e-8f);
        const float invpB = (NSIM >= 2) ? 1.f / (spT.y + 1e-8f) : 0.f;
#pragma unroll
        for (int j = 0; j < 4; j++) {
            int n = tid + 512 * j;
            destA[n] = __float2half_rn(pA[j] * invpA);
            if (NSIM >= 2) destB[n] = __float2half_rn(pB[j] * invpB);
        }
        __syncthreads();
    }
}

__global__ __launch_bounds__(512, 2) __cluster_dims__(2, 1, 1)
void mega_pass(const float* __restrict__ mem, const float* __restrict__ prev_weights) {
    extern __shared__ float smem[];
    const int b = blockIdx.x >> 1;
    const int rank = blockIdx.x & 1;

    pass_body<0>(mem, prev_weights, b, rank, smem);
    __syncthreads();
    pass_body<1>(mem, prev_weights, b, rank, smem);
    __syncthreads();
    pass_body<2>(mem, prev_weights, b, rank, smem);
    __syncthreads();
    pass_body<3>(mem, prev_weights, b, rank, smem);
    __syncthreads();
    pass_body<4>(mem, prev_weights, b, rank, smem);
    // final cluster sync so no CTA exits while peer may still DSMEM-read it
    CLUSTER_SYNC();
}

// ---------------- output epilogue ----------------
__global__ void out_act_kernel(const float* __restrict__ b_out, float* __restrict__ out) {
    int b = blockIdx.x, j = threadIdx.x;
    float v = b_out[j];
#pragma unroll
    for (int sl = 0; sl < 6; sl++)
        v += g_op[((size_t)sl * BB + b) * 256 + j];
    out[(size_t)b * 256 + j] = 1.f / (1.f + expf(-v));
}

// ---------------- launch ----------------
extern "C" void kernel_launch(void* const* d_in, const int* in_sizes, int n_in,
                              void* d_out, int out_size) {
    const float* in_data      = (const float*)d_in[0];
    const float* memory       = (const float*)d_in[1];
    const float* h_prev       = (const float*)d_in[2];
    const float* c_prev       = (const float*)d_in[3];
    const float* prev_reads   = (const float*)d_in[4];
    const float* prev_weights = (const float*)d_in[5];
    const float* W_ih  = (const float*)d_in[6];
    const float* b_ih  = (const float*)d_in[7];
    const float* W_hh  = (const float*)d_in[8];
    const float* b_hh  = (const float*)d_in[9];
    const float* W_out = (const float*)d_in[10];
    const float* b_out = (const float*)d_in[11];
    const float* Wk    = (const float*)d_in[12];
    const float* bk    = (const float*)d_in[13];
    const float* Wbeta = (const float*)d_in[14];
    const float* bbeta = (const float*)d_in[15];
    const float* Wg    = (const float*)d_in[16];
    const float* bg    = (const float*)d_in[17];
    const float* Ws    = (const float*)d_in[18];
    const float* bs    = (const float*)d_in[19];
    const float* Wgam  = (const float*)d_in[20];
    const float* bgam  = (const float*)d_in[21];
    const float* We    = (const float*)d_in[22];
    const float* be    = (const float*)d_in[23];
    const float* Wa    = (const float*)d_in[24];
    const float* ba    = (const float*)d_in[25];
    float* out = (float*)d_out;

    float* gp; cudaGetSymbolAddress((void**)&gp, g_gp);
    float* pp; cudaGetSymbolAddress((void**)&pp, g_pp);
    float* op; cudaGetSymbolAddress((void**)&op, g_op);
    float* gx; cudaGetSymbolAddress((void**)&gx, g_x);
    float* gc; cudaGetSymbolAddress((void**)&gc, g_c);
    float* ghr; cudaGetSymbolAddress((void**)&ghr, g_hr);
    float* gWstk; cudaGetSymbolAddress((void**)&gWstk, g_Wstk);

    cudaFuncSetAttribute(mega_pass, cudaFuncAttributeMaxDynamicSharedMemorySize, MEGA_SMEM);

    // 1. pack x + stacked head weights
    pack_all_kernel<<<(BB * 512 + PR * 512 + 255) / 256, 256>>>(
        in_data, prev_reads, Wk, We, Wa, Ws, Wbeta, Wg, Wgam);

    // 2. LSTM gates + activation
    gemm_gates<<<dim3(32, 2, 8), 256>>>(gx, W_ih, h_prev, W_hh, gp);
    lstm_act_kernel<<<(BB * 128 + 255) / 256, 256>>>(b_ih, b_hh, c_prev);

    // 3. head-param GEMM + activations
    gemm_tn<<<dim3(25, 2, 8), 256>>>(gc, gWstk, pp, PR, 512, 64, 0);
    param_act_kernel<<<BB, 256>>>(bk, be, ba, bs, bbeta, bg, bgam);

    // 4. all 5 memory passes: 2-CTA cluster per batch, all 148 SMs engaged
    mega_pass<<<dim3(2 * BB), 512, MEGA_SMEM>>>(memory, prev_weights);

    // 5. output layer
    gemm_tn<<<dim3(4, 2, 6), 256>>>(ghr, W_out, op, 256, 768, 128, 0);
    out_act_kernel<<<BB, 256>>>(b_out, out);
}

// round 16
// speedup vs baseline: 1.0626x; 1.0626x over previous
#include <cuda_runtime.h>
#include <cuda_fp16.h>
#include <cstdint>
#include <math.h>

#define BB 128
#define NN 4096
#define MM 64
#define PR 1584   // stacked: 512 Wk + 512 We + 512 Wa + 24 Ws + 8 Wbeta + 8 Wg + 8 Wgam

// ---------------- scratch (device globals; no allocations) ----------------
__device__ float g_x[BB * 512];
__device__ float g_c[BB * 512];
__device__ float g_hr[BB * 768];           // [h(512) | read0..3 (4*64)]
__device__ float g_Wstk[PR * 512];
__device__ float g_gp[8 * BB * 2048];      // gates GEMM split-K partials
__device__ float g_pp[8 * BB * PR];        // head-param GEMM partials
__device__ float g_op[6 * BB * 256];       // output GEMM partials
__device__ float g_keyv[8 * BB * MM];
__device__ float g_keynorm[8 * BB];
__device__ float g_ev[8 * BB * MM];
__device__ float g_av[8 * BB * MM];
__device__ float g_beta[8 * BB];
__device__ float g_gv[8 * BB];
__device__ float g_gamma[8 * BB];
__device__ float g_sv[8 * BB * 3];
__device__ __half g_memh[(size_t)BB * NN * MM];  // fp16 cache of original memory

__device__ __forceinline__ float sigf(float x) { return 1.f / (1.f + __expf(-x)); }
__device__ __forceinline__ float softplusf(float x) {
    return fmaxf(x, 0.f) + log1pf(expf(-fabsf(x)));
}

// ---------------- combined pack kernel ----------------
__global__ void pack_all_kernel(const float* __restrict__ in_data,
                                const float* __restrict__ prev_reads,
                                const float* __restrict__ Wk, const float* __restrict__ We,
                                const float* __restrict__ Wa, const float* __restrict__ Ws,
                                const float* __restrict__ Wbeta, const float* __restrict__ Wg,
                                const float* __restrict__ Wgam) {
    int idx = blockIdx.x * blockDim.x + threadIdx.x;
    if (idx < BB * 512) {
        int b = idx >> 9, c = idx & 511;
        float v;
        if (c < 256) v = in_data[b * 256 + c];
        else {
            int k = c - 256, i = k >> 6, m = k & 63;
            v = prev_reads[((size_t)i * BB + b) * MM + m];
        }
        g_x[idx] = v;
        return;
    }
    int j = idx - BB * 512;
    if (j >= PR * 512) return;
    int r = j >> 9, k = j & 511;
    float v;
    if (r < 512)        v = Wk[(size_t)r * 512 + k];
    else if (r < 1024)  v = We[(size_t)(r - 512) * 512 + k];
    else if (r < 1536)  v = Wa[(size_t)(r - 1024) * 512 + k];
    else if (r < 1560)  v = Ws[(size_t)(r - 1536) * 512 + k];
    else if (r < 1568)  v = Wbeta[(size_t)(r - 1560) * 512 + k];
    else if (r < 1576)  v = Wg[(size_t)(r - 1568) * 512 + k];
    else                v = Wgam[(size_t)(r - 1576) * 512 + k];
    g_Wstk[j] = v;
}

// ---------------- split-K SGEMM body ----------------
__device__ __forceinline__ void gemm_body(
    const float* __restrict__ A, const float* __restrict__ W,
    float* __restrict__ Cp, int R, int K, int kChunk, int kStart, int slot,
    int mBase, int rBase)
{
    __shared__ __align__(16) float As[16][68];
    __shared__ __align__(16) float Bs[16][68];
    const int t = threadIdx.x;
    const int tx = t & 15, ty = t >> 4;
    const int loadRow = t >> 2;
    const int loadK = (t & 3) * 4;
    const float* Arow = A + (size_t)(mBase + loadRow) * K;
    const bool wv = (rBase + loadRow) < R;
    const float* Wrow = W + (size_t)(wv ? (rBase + loadRow) : 0) * K;
    float acc[4][4] = {};
    for (int k0 = kStart; k0 < kStart + kChunk; k0 += 16) {
        float4 a4 = *reinterpret_cast<const float4*>(Arow + k0 + loadK);
        float4 w4 = *reinterpret_cast<const float4*>(Wrow + k0 + loadK);
        if (!wv) w4 = make_float4(0.f, 0.f, 0.f, 0.f);
        __syncthreads();
        As[loadK + 0][loadRow] = a4.x; As[loadK + 1][loadRow] = a4.y;
        As[loadK + 2][loadRow] = a4.z; As[loadK + 3][loadRow] = a4.w;
        Bs[loadK + 0][loadRow] = w4.x; Bs[loadK + 1][loadRow] = w4.y;
        Bs[loadK + 2][loadRow] = w4.z; Bs[loadK + 3][loadRow] = w4.w;
        __syncthreads();
#pragma unroll
        for (int kk = 0; kk < 16; kk++) {
            float4 av = *reinterpret_cast<const float4*>(&As[kk][ty * 4]);
            float4 wv4 = *reinterpret_cast<const float4*>(&Bs[kk][tx * 4]);
            float aa[4] = {av.x, av.y, av.z, av.w};
            float ww[4] = {wv4.x, wv4.y, wv4.z, wv4.w};
#pragma unroll
            for (int i = 0; i < 4; i++)
#pragma unroll
                for (int j = 0; j < 4; j++)
                    acc[i][j] = fmaf(aa[i], ww[j], acc[i][j]);
        }
    }
#pragma unroll
    for (int i = 0; i < 4; i++) {
        int m = mBase + ty * 4 + i;
#pragma unroll
        for (int j = 0; j < 4; j++) {
            int r = rBase + tx * 4 + j;
            if (r < R) Cp[((size_t)slot * BB + m) * R + r] = acc[i][j];
        }
    }
}

__global__ __launch_bounds__(256) void gemm_tn(
    const float* __restrict__ A, const float* __restrict__ W,
    float* __restrict__ Cp, int R, int K, int kChunk, int slotBase)
{
    gemm_body(A, W, Cp, R, K, kChunk, blockIdx.z * kChunk, slotBase + blockIdx.z,
              blockIdx.y * 64, blockIdx.x * 64);
}

// both gates GEMMs in one launch: z<4 -> x@W_ih^T (slots 0..3), z>=4 -> h@W_hh^T (slots 4..7)
__global__ __launch_bounds__(256) void gemm_gates(
    const float* __restrict__ A0, const float* __restrict__ W0,
    const float* __restrict__ A1, const float* __restrict__ W1,
    float* __restrict__ Cp)
{
    const int z = blockIdx.z;
    const float* A = (z < 4) ? A0 : A1;
    const float* W = (z < 4) ? W0 : W1;
    gemm_body(A, W, Cp, 2048, 512, 128, (z & 3) * 128, z, blockIdx.y * 64, blockIdx.x * 64);
}

// ---------------- LSTM epilogue (float4 vectorized) ----------------
__global__ void lstm_act_kernel(const float* __restrict__ b_ih, const float* __restrict__ b_hh,
                                const float* __restrict__ c_prev) {
    int idx = blockIdx.x * blockDim.x + threadIdx.x;   // BB*128 threads
    if (idx >= BB * 128) return;
    int b = idx >> 7, j4 = (idx & 127) * 4;
    float4 s[4];
#pragma unroll
    for (int q = 0; q < 4; q++) {
        int col = q * 512 + j4;
        float4 bi = *reinterpret_cast<const float4*>(b_ih + col);
        float4 bh = *reinterpret_cast<const float4*>(b_hh + col);
        s[q] = make_float4(bi.x + bh.x, bi.y + bh.y, bi.z + bh.z, bi.w + bh.w);
    }
#pragma unroll
    for (int sl = 0; sl < 8; sl++) {
        const float* base = g_gp + ((size_t)sl * BB + b) * 2048;
#pragma unroll
        for (int q = 0; q < 4; q++) {
            float4 p = *reinterpret_cast<const float4*>(base + q * 512 + j4);
            s[q].x += p.x; s[q].y += p.y; s[q].z += p.z; s[q].w += p.w;
        }
    }
    float4 cp = *reinterpret_cast<const float4*>(c_prev + b * 512 + j4);
    float cc0 = sigf(s[1].x) * cp.x + sigf(s[0].x) * tanhf(s[2].x);
    float cc1 = sigf(s[1].y) * cp.y + sigf(s[0].y) * tanhf(s[2].y);
    float cc2 = sigf(s[1].z) * cp.z + sigf(s[0].z) * tanhf(s[2].z);
    float cc3 = sigf(s[1].w) * cp.w + sigf(s[0].w) * tanhf(s[2].w);
    *reinterpret_cast<float4*>(g_c + b * 512 + j4) = make_float4(cc0, cc1, cc2, cc3);
    float4 hh = make_float4(sigf(s[3].x) * tanhf(cc0), sigf(s[3].y) * tanhf(cc1),
                            sigf(s[3].z) * tanhf(cc2), sigf(s[3].w) * tanhf(cc3));
    *reinterpret_cast<float4*>(g_hr + (size_t)b * 768 + j4) = hh;
}

// ---------------- head-param epilogue (1 block per batch, coalesced) ----------------
__global__ __launch_bounds__(256) void param_act_kernel(
    const float* __restrict__ bk, const float* __restrict__ be,
    const float* __restrict__ ba, const float* __restrict__ bs,
    const float* __restrict__ bbeta, const float* __restrict__ bg,
    const float* __restrict__ bgam) {
    const int b = blockIdx.x;
    const int t = threadIdx.x;
    __shared__ float s_np[128];   // per-f4 key norm partials
    __shared__ float s_sh[24];    // raw shift logits

    for (int f4 = t; f4 < 396; f4 += 256) {
        int r = f4 * 4;
        float4 v = make_float4(0.f, 0.f, 0.f, 0.f);
#pragma unroll
        for (int sl = 0; sl < 8; sl++) {
            float4 p = *reinterpret_cast<const float4*>(
                g_pp + ((size_t)sl * BB + b) * PR + r);
            v.x += p.x; v.y += p.y; v.z += p.z; v.w += p.w;
        }
        if (r < 512) {
            float4 bb4 = *reinterpret_cast<const float4*>(bk + r);
            v.x += bb4.x; v.y += bb4.y; v.z += bb4.z; v.w += bb4.w;
            int head = r >> 6, m = r & 63;
            *reinterpret_cast<float4*>(g_keyv + ((size_t)head * BB + b) * 64 + m) = v;
            s_np[f4] = v.x * v.x + v.y * v.y + v.z * v.z + v.w * v.w;
        } else if (r < 1024) {
            int rr = r - 512;
            float4 bb4 = *reinterpret_cast<const float4*>(be + rr);
            int head = rr >> 6, m = rr & 63;
            float4 o = make_float4(sigf(v.x + bb4.x), sigf(v.y + bb4.y),
                                   sigf(v.z + bb4.z), sigf(v.w + bb4.w));
            *reinterpret_cast<float4*>(g_ev + ((size_t)head * BB + b) * 64 + m) = o;
        } else if (r < 1536) {
            int rr = r - 1024;
            float4 bb4 = *reinterpret_cast<const float4*>(ba + rr);
            int head = rr >> 6, m = rr & 63;
            float4 o = make_float4(tanhf(v.x + bb4.x), tanhf(v.y + bb4.y),
                                   tanhf(v.z + bb4.z), tanhf(v.w + bb4.w));
            *reinterpret_cast<float4*>(g_av + ((size_t)head * BB + b) * 64 + m) = o;
        } else if (r < 1560) {
            int rr = r - 1536;
            s_sh[rr + 0] = v.x + bs[rr + 0];
            s_sh[rr + 1] = v.y + bs[rr + 1];
            s_sh[rr + 2] = v.z + bs[rr + 2];
            s_sh[rr + 3] = v.w + bs[rr + 3];
        } else if (r < 1568) {
            int rr = r - 1560;
            g_beta[(rr + 0) * BB + b] = softplusf(v.x + bbeta[rr + 0]);
            g_beta[(rr + 1) * BB + b] = softplusf(v.y + bbeta[rr + 1]);
            g_beta[(rr + 2) * BB + b] = softplusf(v.z + bbeta[rr + 2]);
            g_beta[(rr + 3) * BB + b] = softplusf(v.w + bbeta[rr + 3]);
        } else if (r < 1576) {
            int rr = r - 1568;
            g_gv[(rr + 0) * BB + b] = sigf(v.x + bg[rr + 0]);
            g_gv[(rr + 1) * BB + b] = sigf(v.y + bg[rr + 1]);
            g_gv[(rr + 2) * BB + b] = sigf(v.z + bg[rr + 2]);
            g_gv[(rr + 3) * BB + b] = sigf(v.w + bg[rr + 3]);
        } else {
            int rr = r - 1576;
            g_gamma[(rr + 0) * BB + b] = 1.f + softplusf(v.x + bgam[rr + 0]);
            g_gamma[(rr + 1) * BB + b] = 1.f + softplusf(v.y + bgam[rr + 1]);
            g_gamma[(rr + 2) * BB + b] = 1.f + softplusf(v.z + bgam[rr + 2]);
            g_gamma[(rr + 3) * BB + b] = 1.f + softplusf(v.w + bgam[rr + 3]);
        }
    }
    __syncthreads();
    if (t < 8) {
        float s = 0.f;
#pragma unroll
        for (int j = 0; j < 16; j++) s += s_np[t * 16 + j];
        g_keynorm[t * BB + b] = sqrtf(s);
        float x0 = s_sh[t * 3], x1 = s_sh[t * 3 + 1], x2 = s_sh[t * 3 + 2];
        float m = fmaxf(x0, fmaxf(x1, x2));
        float e0 = expf(x0 - m), e1 = expf(x1 - m), e2 = expf(x2 - m);
        float d = e0 + e1 + e2;
        size_t hb = (size_t)t * BB + b;
        g_sv[hb * 3 + 0] = e0 / d;
        g_sv[hb * 3 + 1] = e1 / d;
        g_sv[hb * 3 + 2] = e2 / d;
    }
}

// ---------------- mega pass kernel ----------------
__device__ __forceinline__ float2 blk_reduce_f2(float2 v, float2* red) {
    int lane = threadIdx.x & 31, wid = threadIdx.x >> 5;
#pragma unroll
    for (int off = 16; off >= 1; off >>= 1) {
        v.x += __shfl_xor_sync(0xffffffffu, v.x, off);
        v.y += __shfl_xor_sync(0xffffffffu, v.y, off);
    }
    if (lane == 0) red[wid] = v;
    __syncthreads();
    if (wid == 0) {
        float2 x = red[lane];
#pragma unroll
        for (int off = 16; off >= 1; off >>= 1) {
            x.x += __shfl_xor_sync(0xffffffffu, x.x, off);
            x.y += __shfl_xor_sync(0xffffffffu, x.y, off);
        }
        if (lane == 0) red[0] = x;
    }
    __syncthreads();
    float2 r = red[0];
    __syncthreads();
    return r;
}

__device__ __forceinline__ void upd8(__half2* v, __half2 w2,
                                     const __half2* ne, const __half2* a) {
#pragma unroll
    for (int j = 0; j < 4; j++)
        v[j] = __hfma2(w2, __hfma2(ne[j], v[j], a[j]), v[j]);
}

// packed half2 xor-shuffle add over 8-lane groups (3 levels)
__device__ __forceinline__ __half2 shfl8_hadd2(__half2 p) {
    unsigned u = *reinterpret_cast<unsigned*>(&p);
#pragma unroll
    for (int off = 4; off >= 1; off >>= 1) {
        unsigned o = __shfl_xor_sync(0xffffffffu, u, off);
        __half2 a = *reinterpret_cast<__half2*>(&u);
        __half2 bb = *reinterpret_cast<__half2*>(&o);
        a = __hadd2(a, bb);
        u = *reinterpret_cast<unsigned*>(&a);
    }
    return *reinterpret_cast<__half2*>(&u);
}

// smem bytes: simA 4096f | simB 4096f | wg 2048f | red 64f | whr/wh1/wh3/wh5 4096h each
#define MEGA_SMEM ((4096 * 2 + 2048 + 64) * 4 + 4 * 4096 * 2)

template <int ST>
__device__ void pass_body(const float* __restrict__ mem,
                          const float* __restrict__ prev_weights, int b,
                          float* s_simA, float* s_simB, float* s_wg, float2* s_red,
                          __half* s_whr, __half* s_wh1, __half* s_wh3, __half* s_wh5)
{
    constexpr bool HAS_READ = (ST >= 1);
    constexpr int RIDX = (ST - 1);
    constexpr bool HAS_POST = (ST >= 1 && ST <= 3);
    constexpr int NSIM = (ST <= 2) ? 2 : (ST == 3) ? 1 : 0;
    constexpr int SH0 = 2 * ST;

    const int tid = threadIdx.x;
    const int lane = tid & 31;
    const int warpId = tid >> 5;
    const int sub = lane & 7;
    const int rsel = lane >> 3;

    auto ldh8 = [&](const float* base, int head, __half2* dst, bool neg) {
        const float* p = base + ((size_t)head * BB + b) * 64 + sub * 8;
        float4 f0 = *reinterpret_cast<const float4*>(p);
        float4 f1 = *reinterpret_cast<const float4*>(p + 4);
        dst[0] = __floats2half2_rn(f0.x, f0.y); dst[1] = __floats2half2_rn(f0.z, f0.w);
        dst[2] = __floats2half2_rn(f1.x, f1.y); dst[3] = __floats2half2_rn(f1.z, f1.w);
        if (neg) {
#pragma unroll
            for (int j = 0; j < 4; j++) dst[j] = __hneg2(dst[j]);
        }
    };

    __half2 ne1[4], a1[4], ne3[4], a3[4], ne5[4], a5[4], k0[4], k1[4];
    float kn0 = 0.f, kn1 = 0.f;
    if (ST >= 1) { ldh8(g_ev, 1, ne1, true); ldh8(g_av, 1, a1, false); }
    if (ST >= 2) { ldh8(g_ev, 3, ne3, true); ldh8(g_av, 3, a3, false); }
    if (ST >= 3) { ldh8(g_ev, 5, ne5, true); ldh8(g_av, 5, a5, false); }
    if (NSIM >= 1) { ldh8(g_keyv, SH0, k0, false); kn0 = g_keynorm[SH0 * BB + b]; }
    if (NSIM >= 2) { ldh8(g_keyv, SH0 + 1, k1, false); kn1 = g_keynorm[(SH0 + 1) * BB + b]; }

    float racc[8] = {};
    __half2 racc2[4] = {__floats2half2_rn(0.f, 0.f), __floats2half2_rn(0.f, 0.f),
                        __floats2half2_rn(0.f, 0.f), __floats2half2_rn(0.f, 0.f)};
    const size_t bn = (size_t)b * NN;
    const int rowInBlk = warpId * 4 + rsel;

    // ---- phase A with prefetch + half weights + windowed read accumulation ----
    uint4 cu = make_uint4(0, 0, 0, 0);
    float4 cf0 = make_float4(0, 0, 0, 0), cf1 = cf0;
    __half cwrh = __float2half_rn(0.f), cw1h = cwrh, cw3h = cwrh, cw5h = cwrh;
    {
        const int n = rowInBlk;
        const size_t hidx = (bn + n) * 64 + sub * 8;
        if (ST == 0) {
            cf0 = __ldcs(reinterpret_cast<const float4*>(mem + hidx));
            cf1 = __ldcs(reinterpret_cast<const float4*>(mem + hidx + 4));
        } else {
            cu = __ldg(reinterpret_cast<const uint4*>(g_memh + hidx));
        }
        if (ST >= 1) { cwrh = s_whr[n]; cw1h = s_wh1[n]; }
        if (ST >= 2) cw3h = s_wh3[n];
        if (ST >= 3) cw5h = s_wh5[n];
    }

#pragma unroll 4
    for (int it = 0; it < 32; it++) {
        const int n = it * 128 + rowInBlk;
        const int n2 = (it < 31) ? (n + 128) : rowInBlk;   // wrap-safe prefetch index
        uint4 nu = make_uint4(0, 0, 0, 0);
        float4 nf0 = make_float4(0, 0, 0, 0), nf1 = nf0;
        __half nwrh = __float2half_rn(0.f), nw1h = nwrh, nw3h = nwrh, nw5h = nwrh;
        {
            const size_t hidx2 = (bn + n2) * 64 + sub * 8;
            if (ST == 0) {
                nf0 = __ldcs(reinterpret_cast<const float4*>(mem + hidx2));
                nf1 = __ldcs(reinterpret_cast<const float4*>(mem + hidx2 + 4));
            } else {
                nu = __ldg(reinterpret_cast<const uint4*>(g_memh + hidx2));
            }
            if (ST >= 1) { nwrh = s_whr[n2]; nw1h = s_wh1[n2]; }
            if (ST >= 2) nw3h = s_wh3[n2];
            if (ST >= 3) nw5h = s_wh5[n2];
        }
        // compute current
        __half2 v[4];
        if (ST == 0) {
            v[0] = __floats2half2_rn(cf0.x, cf0.y); v[1] = __floats2half2_rn(cf0.z, cf0.w);
            v[2] = __floats2half2_rn(cf1.x, cf1.y); v[3] = __floats2half2_rn(cf1.z, cf1.w);
            const size_t hidx = (bn + n) * 64 + sub * 8;
            *reinterpret_cast<uint4*>(g_memh + hidx) = *reinterpret_cast<uint4*>(v);
        } else {
            *reinterpret_cast<uint4*>(v) = cu;
        }
        if (ST >= 2) upd8(v, __half2half2(cw1h), ne1, a1);
        if (ST >= 3) upd8(v, __half2half2(cw3h), ne3, a3);
        if (ST == 4) upd8(v, __half2half2(cw5h), ne5, a5);
        if (HAS_READ) {
            __half2 w2r = __half2half2(cwrh);
#pragma unroll
            for (int j = 0; j < 4; j++)
                racc2[j] = __hfma2(w2r, v[j], racc2[j]);
            if ((it & 3) == 3) {   // static under unroll 4: flush window to fp32
#pragma unroll
                for (int j = 0; j < 4; j++) {
                    float2 f = __half22float2(racc2[j]);
                    racc[2 * j] += f.x; racc[2 * j + 1] += f.y;
                    racc2[j] = __floats2half2_rn(0.f, 0.f);
                }
            }
        }
        if (HAS_POST) {
            __half pwh = (ST == 1) ? cw1h : (ST == 2) ? cw3h : cw5h;
            const __half2* pne = (ST == 1) ? ne1 : (ST == 2) ? ne3 : ne5;
            const __half2* pa  = (ST == 1) ? a1  : (ST == 2) ? a3  : a5;
            upd8(v, __half2half2(pwh), pne, pa);
        }
        if (NSIM >= 1) {
            __half2 ns2 = __floats2half2_rn(0.f, 0.f);
            __half2 d02 = ns2, d12 = ns2;
#pragma unroll
            for (int j = 0; j < 4; j++) {
                ns2 = __hfma2(v[j], v[j], ns2);
                d02 = __hfma2(v[j], k0[j], d02);
                if (NSIM >= 2) d12 = __hfma2(v[j], k1[j], d12);
            }
            float2 nsf = __half22float2(ns2);
            float2 d0f2 = __half22float2(d02);
            float ns = nsf.x + nsf.y;
            float d0 = d0f2.x + d0f2.y;
            if (NSIM >= 2) {
                // pack (d0, d1) as half2, reduce with 3 shuffles; ns in fp32 (3 shuffles)
                float2 d1f2 = __half22float2(d12);
                float d1 = d1f2.x + d1f2.y;
                __half2 pd = __floats2half2_rn(d0, d1);
#pragma unroll
                for (int off = 4; off >= 1; off >>= 1)
                    ns += __shfl_xor_sync(0xffffffffu, ns, off);
                pd = shfl8_hadd2(pd);
                if (sub == 0) {
                    float2 dd = __half22float2(pd);
                    float nm = sqrtf(ns);
                    s_simA[n] = dd.x / (nm * kn0 + 1e-8f);
                    s_simB[n] = dd.y / (nm * kn1 + 1e-8f);
                }
            } else {
                // pack (ns, d0) as half2, single 3-shuffle reduction
                __half2 pd = __floats2half2_rn(ns, d0);
                pd = shfl8_hadd2(pd);
                if (sub == 0) {
                    float2 dd = __half22float2(pd);
                    float nm = sqrtf(dd.x);
                    s_simA[n] = dd.y / (nm * kn0 + 1e-8f);
                }
            }
        }
        cu = nu; cf0 = nf0; cf1 = nf1;
        cwrh = nwrh; cw1h = nw1h; cw3h = nw3h; cw5h = nw5h;
    }

    // ---- in-block read reduction -> g_hr ----
    if (HAS_READ) {
        __syncthreads();
#pragma unroll
        for (int j = 0; j < 8; j++) {
            racc[j] += __shfl_down_sync(0xffffffffu, racc[j], 16);
            racc[j] += __shfl_down_sync(0xffffffffu, racc[j], 8);
        }
        if (lane < 8) {
#pragma unroll
            for (int j = 0; j < 8; j++)
                s_wg[warpId * 64 + sub * 8 + j] = racc[j];
        }
        __syncthreads();
        if (tid < 64) {
            float s = 0.f;
#pragma unroll
            for (int w = 0; w < 32; w++) s += s_wg[w * 64 + tid];
            g_hr[(size_t)b * 768 + 512 + RIDX * 64 + tid] = s;
        }
    }
    __syncthreads();

    // ---- phase B: weights (both heads fused), write half weights ----
    if (NSIM >= 1) {
        const int hbA = SH0 * BB + b;
        const int hbB = (SH0 + 1) * BB + b;
        __half* destA = s_whr;
        __half* destB = (ST == 0) ? s_wh1 : (ST == 1) ? s_wh3 : s_wh5;
        const float* pwA = prev_weights + (size_t)hbA * NN;
        const float* pwB = prev_weights + (size_t)hbB * NN;
        const float betaA = g_beta[hbA], ggA = g_gv[hbA], gamA = g_gamma[hbA];
        const float sA0 = g_sv[(size_t)hbA * 3 + 0];
        const float sA1 = g_sv[(size_t)hbA * 3 + 1];
        const float sA2 = g_sv[(size_t)hbA * 3 + 2];
        float betaB = 0.f, ggB = 0.f, gamB = 1.f, sB0 = 0.f, sB1 = 0.f, sB2 = 0.f;
        if (NSIM >= 2) {
            betaB = g_beta[hbB]; ggB = g_gv[hbB]; gamB = g_gamma[hbB];
            sB0 = g_sv[(size_t)hbB * 3 + 0];
            sB1 = g_sv[(size_t)hbB * 3 + 1];
            sB2 = g_sv[(size_t)hbB * 3 + 2];
        }

        float exA[4], exB[4];
        float2 se = make_float2(0.f, 0.f);
#pragma unroll
        for (int j = 0; j < 4; j++) {
            int n = tid + 1024 * j;
            exA[j] = __expf(betaA * s_simA[n]); se.x += exA[j];
            if (NSIM >= 2) { exB[j] = __expf(betaB * s_simB[n]); se.y += exB[j]; }
        }
        se = blk_reduce_f2(se, s_red);
        const float invA = 1.f / se.x;
        const float invB = (NSIM >= 2) ? 1.f / se.y : 0.f;
#pragma unroll
        for (int j = 0; j < 4; j++) {
            int n = tid + 1024 * j;
            s_simA[n] = ggA * (exA[j] * invA) + (1.f - ggA) * pwA[n];
            if (NSIM >= 2) s_simB[n] = ggB * (exB[j] * invB) + (1.f - ggB) * pwB[n];
        }
        __syncthreads();
        float pA[4], pB[4];
        float2 sp = make_float2(0.f, 0.f);
#pragma unroll
        for (int j = 0; j < 4; j++) {
            int n = tid + 1024 * j;
            int np = (n + 1) & (NN - 1), nm = (n - 1) & (NN - 1);
            float wsA = sA0 * s_simA[np] + sA1 * s_simA[n] + sA2 * s_simA[nm];
            pA[j] = __powf(wsA, gamA); sp.x += pA[j];
            if (NSIM >= 2) {
                float wsB = sB0 * s_simB[np] + sB1 * s_simB[n] + sB2 * s_simB[nm];
                pB[j] = __powf(wsB, gamB); sp.y += pB[j];
            }
        }
        sp = blk_reduce_f2(sp, s_red);
        const float invpA = 1.f / (sp.x + 1e-8f);
        const float invpB = (NSIM >= 2) ? 1.f / (sp.y + 1e-8f) : 0.f;
#pragma unroll
        for (int j = 0; j < 4; j++) {
            int n = tid + 1024 * j;
            destA[n] = __float2half_rn(pA[j] * invpA);
            if (NSIM >= 2) destB[n] = __float2half_rn(pB[j] * invpB);
        }
        __syncthreads();
    }
}

__global__ __launch_bounds__(1024, 1) void mega_pass(const float* __restrict__ mem,
                                                     const float* __restrict__ prev_weights) {
    extern __shared__ float smem[];
    float* s_simA = smem;
    float* s_simB = smem + 4096;
    float* s_wg   = smem + 8192;
    float2* s_red = reinterpret_cast<float2*>(smem + 10240);
    __half* s_whr = reinterpret_cast<__half*>(smem + 10304);
    __half* s_wh1 = s_whr + 4096;
    __half* s_wh3 = s_wh1 + 4096;
    __half* s_wh5 = s_wh3 + 4096;
    const int b = blockIdx.x;

    pass_body<0>(mem, prev_weights, b, s_simA, s_simB, s_wg, s_red, s_whr, s_wh1, s_wh3, s_wh5);
    __syncthreads();
    pass_body<1>(mem, prev_weights, b, s_simA, s_simB, s_wg, s_red, s_whr, s_wh1, s_wh3, s_wh5);
    __syncthreads();
    pass_body<2>(mem, prev_weights, b, s_simA, s_simB, s_wg, s_red, s_whr, s_wh1, s_wh3, s_wh5);
    __syncthreads();
    pass_body<3>(mem, prev_weights, b, s_simA, s_simB, s_wg, s_red, s_whr, s_wh1, s_wh3, s_wh5);
    __syncthreads();
    pass_body<4>(mem, prev_weights, b, s_simA, s_simB, s_wg, s_red, s_whr, s_wh1, s_wh3, s_wh5);
}

// ---------------- output epilogue ----------------
__global__ void out_act_kernel(const float* __restrict__ b_out, float* __restrict__ out) {
    int b = blockIdx.x, j = threadIdx.x;  // 256 threads
    float v = b_out[j];
#pragma unroll
    for (int sl = 0; sl < 6; sl++)
        v += g_op[((size_t)sl * BB + b) * 256 + j];
    out[(size_t)b * 256 + j] = 1.f / (1.f + expf(-v));
}

// ---------------- launch ----------------
extern "C" void kernel_launch(void* const* d_in, const int* in_sizes, int n_in,
                              void* d_out, int out_size) {
    const float* in_data      = (const float*)d_in[0];
    const float* memory       = (const float*)d_in[1];
    const float* h_prev       = (const float*)d_in[2];
    const float* c_prev       = (const float*)d_in[3];
    const float* prev_reads   = (const float*)d_in[4];
    const float* prev_weights = (const float*)d_in[5];
    const float* W_ih  = (const float*)d_in[6];
    const float* b_ih  = (const float*)d_in[7];
    const float* W_hh  = (const float*)d_in[8];
    const float* b_hh  = (const float*)d_in[9];
    const float* W_out = (const float*)d_in[10];
    const float* b_out = (const float*)d_in[11];
    const float* Wk    = (const float*)d_in[12];
    const float* bk    = (const float*)d_in[13];
    const float* Wbeta = (const float*)d_in[14];
    const float* bbeta = (const float*)d_in[15];
    const float* Wg    = (const float*)d_in[16];
    const float* bg    = (const float*)d_in[17];
    const float* Ws    = (const float*)d_in[18];
    const float* bs    = (const float*)d_in[19];
    const float* Wgam  = (const float*)d_in[20];
    const float* bgam  = (const float*)d_in[21];
    const float* We    = (const float*)d_in[22];
    const float* be    = (const float*)d_in[23];
    const float* Wa    = (const float*)d_in[24];
    const float* ba    = (const float*)d_in[25];
    float* out = (float*)d_out;

    float* gp; cudaGetSymbolAddress((void**)&gp, g_gp);
    float* pp; cudaGetSymbolAddress((void**)&pp, g_pp);
    float* op; cudaGetSymbolAddress((void**)&op, g_op);
    float* gx; cudaGetSymbolAddress((void**)&gx, g_x);
    float* gc; cudaGetSymbolAddress((void**)&gc, g_c);
    float* ghr; cudaGetSymbolAddress((void**)&ghr, g_hr);
    float* gWstk; cudaGetSymbolAddress((void**)&gWstk, g_Wstk);

    cudaFuncSetAttribute(mega_pass, cudaFuncAttributeMaxDynamicSharedMemorySize, MEGA_SMEM);

    // 1. pack x + stacked head weights
    pack_all_kernel<<<(BB * 512 + PR * 512 + 255) / 256, 256>>>(
        in_data, prev_reads, Wk, We, Wa, Ws, Wbeta, Wg, Wgam);

    // 2. LSTM gates (both GEMMs in one launch, 8 split-K slots) + activation
    gemm_gates<<<dim3(32, 2, 8), 256>>>(gx, W_ih, h_prev, W_hh, gp);
    lstm_act_kernel<<<(BB * 128 + 255) / 256, 256>>>(b_ih, b_hh, c_prev);

    // 3. head-param GEMM (8 split-K slots, 400 blocks) + activations
    gemm_tn<<<dim3(25, 2, 8), 256>>>(gc, gWstk, pp, PR, 512, 64, 0);
    param_act_kernel<<<BB, 256>>>(bk, be, ba, bs, bbeta, bg, bgam);

    // 4. all 5 memory passes in ONE kernel
    mega_pass<<<BB, 1024, MEGA_SMEM>>>(memory, prev_weights);

    // 5. output layer
    gemm_tn<<<dim3(4, 2, 6), 256>>>(ghr, W_out, op, 256, 768, 128, 0);
    out_act_kernel<<<BB, 256>>>(b_out, out);
}

// round 17
// speedup vs baseline: 1.0790x; 1.0154x over previous
#include <cuda_runtime.h>
#include <cuda_fp16.h>
#include <cstdint>
#include <math.h>

#define BB 128
#define NN 4096
#define MM 64
#define PR 1584   // stacked: 512 Wk + 512 We + 512 Wa + 24 Ws + 8 Wbeta + 8 Wg + 8 Wgam

// ---------------- scratch (device globals; no allocations) ----------------
__device__ float g_c[BB * 512];
__device__ float g_hr[BB * 768];           // [h(512) | read0..3 (4*64)]
__device__ float g_gp[8 * BB * 2048];      // gates GEMM split-K partials
__device__ float g_pp[8 * BB * PR];        // head-param GEMM partials
__device__ float g_op[6 * BB * 256];       // output GEMM partials
__device__ float g_keyv[8 * BB * MM];
__device__ float g_keynorm[8 * BB];
__device__ float g_ev[8 * BB * MM];
__device__ float g_av[8 * BB * MM];
__device__ float g_beta[8 * BB];
__device__ float g_gv[8 * BB];
__device__ float g_gamma[8 * BB];
__device__ float g_sv[8 * BB * 3];
__device__ __half g_memh[(size_t)BB * NN * MM];  // fp16 cache of original memory

__device__ __forceinline__ float sigf(float x) { return 1.f / (1.f + __expf(-x)); }
__device__ __forceinline__ float softplusf(float x) {
    return fmaxf(x, 0.f) + log1pf(expf(-fabsf(x)));
}

// ---------------- split-K SGEMM body (A-load and W-row pointer provided) ----------------
struct GemmSmem { float As[16][68]; float Bs[16][68]; };

// generic: A row-major [., K], W rows via base pointer
__device__ __forceinline__ void gemm_core(
    GemmSmem& sm, const float* Arow, const float* Wrow, bool wv,
    float* __restrict__ Cp, int R, int kChunk, int kStart, int slot,
    int mBase, int rBase, int K)
{
    const int t = threadIdx.x;
    const int tx = t & 15, ty = t >> 4;
    const int loadRow = t >> 2;
    const int loadK = (t & 3) * 4;
    float acc[4][4] = {};
    for (int k0 = kStart; k0 < kStart + kChunk; k0 += 16) {
        float4 a4 = *reinterpret_cast<const float4*>(Arow + k0 + loadK);
        float4 w4 = *reinterpret_cast<const float4*>(Wrow + k0 + loadK);
        if (!wv) w4 = make_float4(0.f, 0.f, 0.f, 0.f);
        __syncthreads();
        sm.As[loadK + 0][loadRow] = a4.x; sm.As[loadK + 1][loadRow] = a4.y;
        sm.As[loadK + 2][loadRow] = a4.z; sm.As[loadK + 3][loadRow] = a4.w;
        sm.Bs[loadK + 0][loadRow] = w4.x; sm.Bs[loadK + 1][loadRow] = w4.y;
        sm.Bs[loadK + 2][loadRow] = w4.z; sm.Bs[loadK + 3][loadRow] = w4.w;
        __syncthreads();
#pragma unroll
        for (int kk = 0; kk < 16; kk++) {
            float4 av = *reinterpret_cast<const float4*>(&sm.As[kk][ty * 4]);
            float4 wv4 = *reinterpret_cast<const float4*>(&sm.Bs[kk][tx * 4]);
            float aa[4] = {av.x, av.y, av.z, av.w};
            float ww[4] = {wv4.x, wv4.y, wv4.z, wv4.w};
#pragma unroll
            for (int i = 0; i < 4; i++)
#pragma unroll
                for (int j = 0; j < 4; j++)
                    acc[i][j] = fmaf(aa[i], ww[j], acc[i][j]);
        }
    }
#pragma unroll
    for (int i = 0; i < 4; i++) {
        int m = mBase + ty * 4 + i;
#pragma unroll
        for (int j = 0; j < 4; j++) {
            int r = rBase + tx * 4 + j;
            if (r < R) Cp[((size_t)slot * BB + m) * R + r] = acc[i][j];
        }
    }
}

// generic split-K (used for output layer)
__global__ __launch_bounds__(256) void gemm_tn(
    const float* __restrict__ A, const float* __restrict__ W,
    float* __restrict__ Cp, int R, int K, int kChunk, int slotBase)
{
    __shared__ __align__(16) GemmSmem sm;
    const int loadRow = threadIdx.x >> 2;
    const int mBase = blockIdx.y * 64, rBase = blockIdx.x * 64;
    const float* Arow = A + (size_t)(mBase + loadRow) * K;
    const bool wv = (rBase + loadRow) < R;
    const float* Wrow = W + (size_t)(wv ? (rBase + loadRow) : 0) * K;
    gemm_core(sm, Arow, Wrow, wv, Cp, R, kChunk, blockIdx.z * kChunk,
              slotBase + blockIdx.z, mBase, rBase, K);
}

// gates GEMM with inline x-gather: z<4 -> [in_data|prev_reads]@W_ih^T, z>=4 -> h@W_hh^T
__global__ __launch_bounds__(256) void gemm_gates(
    const float* __restrict__ in_data, const float* __restrict__ prev_reads,
    const float* __restrict__ h_prev,
    const float* __restrict__ W_ih, const float* __restrict__ W_hh,
    float* __restrict__ Cp)
{
    __shared__ __align__(16) GemmSmem sm;
    const int z = blockIdx.z;
    const bool xpart = (z < 4);
    const int kStart = (z & 3) * 128;
    const int t = threadIdx.x;
    const int tx = t & 15, ty = t >> 4;
    const int mBase = blockIdx.y * 64, rBase = blockIdx.x * 64;
    const int loadRow = t >> 2;
    const int loadK = (t & 3) * 4;
    const int mRow = mBase + loadRow;
    const float* Wrow = (xpart ? W_ih : W_hh) + (size_t)(rBase + loadRow) * 512;
    float acc[4][4] = {};
    for (int k0 = kStart; k0 < kStart + 128; k0 += 16) {
        const int k = k0 + loadK;
        float4 a4;
        if (xpart) {
            if (k < 256) a4 = *reinterpret_cast<const float4*>(in_data + (size_t)mRow * 256 + k);
            else {
                int kk = k - 256;
                a4 = *reinterpret_cast<const float4*>(
                    prev_reads + ((size_t)(kk >> 6) * BB + mRow) * 64 + (kk & 63));
            }
        } else {
            a4 = *reinterpret_cast<const float4*>(h_prev + (size_t)mRow * 512 + k);
        }
        float4 w4 = *reinterpret_cast<const float4*>(Wrow + k);
        __syncthreads();
        sm.As[loadK + 0][loadRow] = a4.x; sm.As[loadK + 1][loadRow] = a4.y;
        sm.As[loadK + 2][loadRow] = a4.z; sm.As[loadK + 3][loadRow] = a4.w;
        sm.Bs[loadK + 0][loadRow] = w4.x; sm.Bs[loadK + 1][loadRow] = w4.y;
        sm.Bs[loadK + 2][loadRow] = w4.z; sm.Bs[loadK + 3][loadRow] = w4.w;
        __syncthreads();
#pragma unroll
        for (int kk = 0; kk < 16; kk++) {
            float4 av = *reinterpret_cast<const float4*>(&sm.As[kk][ty * 4]);
            float4 wv4 = *reinterpret_cast<const float4*>(&sm.Bs[kk][tx * 4]);
            float aa[4] = {av.x, av.y, av.z, av.w};
            float ww[4] = {wv4.x, wv4.y, wv4.z, wv4.w};
#pragma unroll
            for (int i = 0; i < 4; i++)
#pragma unroll
                for (int j = 0; j < 4; j++)
                    acc[i][j] = fmaf(aa[i], ww[j], acc[i][j]);
        }
    }
#pragma unroll
    for (int i = 0; i < 4; i++) {
        int m = mBase + ty * 4 + i;
#pragma unroll
        for (int j = 0; j < 4; j++)
            Cp[((size_t)z * BB + m) * 2048 + rBase + tx * 4 + j] = acc[i][j];
    }
}

// param GEMM with inline stacked-W row gather
__global__ __launch_bounds__(256) void gemm_param(
    const float* __restrict__ Wk, const float* __restrict__ We,
    const float* __restrict__ Wa, const float* __restrict__ Ws,
    const float* __restrict__ Wbeta, const float* __restrict__ Wg,
    const float* __restrict__ Wgam, float* __restrict__ Cp)
{
    __shared__ __align__(16) GemmSmem sm;
    const int loadRow = threadIdx.x >> 2;
    const int mBase = blockIdx.y * 64, rBase = blockIdx.x * 64;
    const int r = rBase + loadRow;
    const bool wv = (r < PR);
    const int rr = wv ? r : 0;
    const float* Wrow;
    if (rr < 512)        Wrow = Wk + (size_t)rr * 512;
    else if (rr < 1024)  Wrow = We + (size_t)(rr - 512) * 512;
    else if (rr < 1536)  Wrow = Wa + (size_t)(rr - 1024) * 512;
    else if (rr < 1560)  Wrow = Ws + (size_t)(rr - 1536) * 512;
    else if (rr < 1568)  Wrow = Wbeta + (size_t)(rr - 1560) * 512;
    else if (rr < 1576)  Wrow = Wg + (size_t)(rr - 1568) * 512;
    else                 Wrow = Wgam + (size_t)(rr - 1576) * 512;
    const float* Arow = g_c + (size_t)(mBase + loadRow) * 512;
    gemm_core(sm, Arow, Wrow, wv, Cp, PR, 64, blockIdx.z * 64, blockIdx.z,
              mBase, rBase, 512);
}

// ---------------- LSTM epilogue (float4 vectorized) ----------------
__global__ void lstm_act_kernel(const float* __restrict__ b_ih, const float* __restrict__ b_hh,
                                const float* __restrict__ c_prev) {
    int idx = blockIdx.x * blockDim.x + threadIdx.x;   // BB*128 threads
    if (idx >= BB * 128) return;
    int b = idx >> 7, j4 = (idx & 127) * 4;
    float4 s[4];
#pragma unroll
    for (int q = 0; q < 4; q++) {
        int col = q * 512 + j4;
        float4 bi = *reinterpret_cast<const float4*>(b_ih + col);
        float4 bh = *reinterpret_cast<const float4*>(b_hh + col);
        s[q] = make_float4(bi.x + bh.x, bi.y + bh.y, bi.z + bh.z, bi.w + bh.w);
    }
#pragma unroll
    for (int sl = 0; sl < 8; sl++) {
        const float* base = g_gp + ((size_t)sl * BB + b) * 2048;
#pragma unroll
        for (int q = 0; q < 4; q++) {
            float4 p = *reinterpret_cast<const float4*>(base + q * 512 + j4);
            s[q].x += p.x; s[q].y += p.y; s[q].z += p.z; s[q].w += p.w;
        }
    }
    float4 cp = *reinterpret_cast<const float4*>(c_prev + b * 512 + j4);
    float cc0 = sigf(s[1].x) * cp.x + sigf(s[0].x) * tanhf(s[2].x);
    float cc1 = sigf(s[1].y) * cp.y + sigf(s[0].y) * tanhf(s[2].y);
    float cc2 = sigf(s[1].z) * cp.z + sigf(s[0].z) * tanhf(s[2].z);
    float cc3 = sigf(s[1].w) * cp.w + sigf(s[0].w) * tanhf(s[2].w);
    *reinterpret_cast<float4*>(g_c + b * 512 + j4) = make_float4(cc0, cc1, cc2, cc3);
    float4 hh = make_float4(sigf(s[3].x) * tanhf(cc0), sigf(s[3].y) * tanhf(cc1),
                            sigf(s[3].z) * tanhf(cc2), sigf(s[3].w) * tanhf(cc3));
    *reinterpret_cast<float4*>(g_hr + (size_t)b * 768 + j4) = hh;
}

// ---------------- mega pass kernel (with param-act prologue) ----------------
__device__ __forceinline__ float2 blk_reduce_f2(float2 v, float2* red) {
    int lane = threadIdx.x & 31, wid = threadIdx.x >> 5;
#pragma unroll
    for (int off = 16; off >= 1; off >>= 1) {
        v.x += __shfl_xor_sync(0xffffffffu, v.x, off);
        v.y += __shfl_xor_sync(0xffffffffu, v.y, off);
    }
    if (lane == 0) red[wid] = v;
    __syncthreads();
    if (wid == 0) {
        float2 x = red[lane];
#pragma unroll
        for (int off = 16; off >= 1; off >>= 1) {
            x.x += __shfl_xor_sync(0xffffffffu, x.x, off);
            x.y += __shfl_xor_sync(0xffffffffu, x.y, off);
        }
        if (lane == 0) red[0] = x;
    }
    __syncthreads();
    float2 r = red[0];
    __syncthreads();
    return r;
}

__device__ __forceinline__ void upd8(__half2* v, __half2 w2,
                                     const __half2* ne, const __half2* a) {
#pragma unroll
    for (int j = 0; j < 4; j++)
        v[j] = __hfma2(w2, __hfma2(ne[j], v[j], a[j]), v[j]);
}

__device__ __forceinline__ __half2 shfl8_hadd2(__half2 p) {
    unsigned u = *reinterpret_cast<unsigned*>(&p);
#pragma unroll
    for (int off = 4; off >= 1; off >>= 1) {
        unsigned o = __shfl_xor_sync(0xffffffffu, u, off);
        __half2 a = *reinterpret_cast<__half2*>(&u);
        __half2 bb = *reinterpret_cast<__half2*>(&o);
        a = __hadd2(a, bb);
        u = *reinterpret_cast<unsigned*>(&a);
    }
    return *reinterpret_cast<__half2*>(&u);
}

// smem bytes: simA 4096f | simB 4096f | wg 2048f | red 64f | whr/wh1/wh3/wh5 4096h each
#define MEGA_SMEM ((4096 * 2 + 2048 + 64) * 4 + 4 * 4096 * 2)

// param-act prologue: block b computes batch b's head params from g_pp
__device__ void param_act_body(int b, float* s_np, float* s_sh,
                               const float* __restrict__ bk, const float* __restrict__ be,
                               const float* __restrict__ ba, const float* __restrict__ bs,
                               const float* __restrict__ bbeta, const float* __restrict__ bg,
                               const float* __restrict__ bgam) {
    const int t = threadIdx.x;
    for (int f4 = t; f4 < 396; f4 += 1024) {
        int r = f4 * 4;
        float4 v = make_float4(0.f, 0.f, 0.f, 0.f);
#pragma unroll
        for (int sl = 0; sl < 8; sl++) {
            float4 p = *reinterpret_cast<const float4*>(
                g_pp + ((size_t)sl * BB + b) * PR + r);
            v.x += p.x; v.y += p.y; v.z += p.z; v.w += p.w;
        }
        if (r < 512) {
            float4 bb4 = *reinterpret_cast<const float4*>(bk + r);
            v.x += bb4.x; v.y += bb4.y; v.z += bb4.z; v.w += bb4.w;
            int head = r >> 6, m = r & 63;
            *reinterpret_cast<float4*>(g_keyv + ((size_t)head * BB + b) * 64 + m) = v;
            s_np[f4] = v.x * v.x + v.y * v.y + v.z * v.z + v.w * v.w;
        } else if (r < 1024) {
            int rr = r - 512;
            float4 bb4 = *reinterpret_cast<const float4*>(be + rr);
            int head = rr >> 6, m = rr & 63;
            float4 o = make_float4(sigf(v.x + bb4.x), sigf(v.y + bb4.y),
                                   sigf(v.z + bb4.z), sigf(v.w + bb4.w));
            *reinterpret_cast<float4*>(g_ev + ((size_t)head * BB + b) * 64 + m) = o;
        } else if (r < 1536) {
            int rr = r - 1024;
            float4 bb4 = *reinterpret_cast<const float4*>(ba + rr);
            int head = rr >> 6, m = rr & 63;
            float4 o = make_float4(tanhf(v.x + bb4.x), tanhf(v.y + bb4.y),
                                   tanhf(v.z + bb4.z), tanhf(v.w + bb4.w));
            *reinterpret_cast<float4*>(g_av + ((size_t)head * BB + b) * 64 + m) = o;
        } else if (r < 1560) {
            int rr = r - 1536;
            s_sh[rr + 0] = v.x + bs[rr + 0];
            s_sh[rr + 1] = v.y + bs[rr + 1];
            s_sh[rr + 2] = v.z + bs[rr + 2];
            s_sh[rr + 3] = v.w + bs[rr + 3];
        } else if (r < 1568) {
            int rr = r - 1560;
            g_beta[(rr + 0) * BB + b] = softplusf(v.x + bbeta[rr + 0]);
            g_beta[(rr + 1) * BB + b] = softplusf(v.y + bbeta[rr + 1]);
            g_beta[(rr + 2) * BB + b] = softplusf(v.z + bbeta[rr + 2]);
            g_beta[(rr + 3) * BB + b] = softplusf(v.w + bbeta[rr + 3]);
        } else if (r < 1576) {
            int rr = r - 1568;
            g_gv[(rr + 0) * BB + b] = sigf(v.x + bg[rr + 0]);
            g_gv[(rr + 1) * BB + b] = sigf(v.y + bg[rr + 1]);
            g_gv[(rr + 2) * BB + b] = sigf(v.z + bg[rr + 2]);
            g_gv[(rr + 3) * BB + b] = sigf(v.w + bg[rr + 3]);
        } else {
            int rr = r - 1576;
            g_gamma[(rr + 0) * BB + b] = 1.f + softplusf(v.x + bgam[rr + 0]);
            g_gamma[(rr + 1) * BB + b] = 1.f + softplusf(v.y + bgam[rr + 1]);
            g_gamma[(rr + 2) * BB + b] = 1.f + softplusf(v.z + bgam[rr + 2]);
            g_gamma[(rr + 3) * BB + b] = 1.f + softplusf(v.w + bgam[rr + 3]);
        }
    }
    __syncthreads();
    if (t < 8) {
        float s = 0.f;
#pragma unroll
        for (int j = 0; j < 16; j++) s += s_np[t * 16 + j];
        g_keynorm[t * BB + b] = sqrtf(s);
        float x0 = s_sh[t * 3], x1 = s_sh[t * 3 + 1], x2 = s_sh[t * 3 + 2];
        float m = fmaxf(x0, fmaxf(x1, x2));
        float e0 = expf(x0 - m), e1 = expf(x1 - m), e2 = expf(x2 - m);
        float d = e0 + e1 + e2;
        size_t hb = (size_t)t * BB + b;
        g_sv[hb * 3 + 0] = e0 / d;
        g_sv[hb * 3 + 1] = e1 / d;
        g_sv[hb * 3 + 2] = e2 / d;
    }
    __syncthreads();
}

template <int ST>
__device__ void pass_body(const float* __restrict__ mem,
                          const float* __restrict__ prev_weights, int b,
                          float* s_simA, float* s_simB, float* s_wg, float2* s_red,
                          __half* s_whr, __half* s_wh1, __half* s_wh3, __half* s_wh5)
{
    constexpr bool HAS_READ = (ST >= 1);
    constexpr int RIDX = (ST - 1);
    constexpr bool HAS_POST = (ST >= 1 && ST <= 3);
    constexpr int NSIM = (ST <= 2) ? 2 : (ST == 3) ? 1 : 0;
    constexpr int SH0 = 2 * ST;

    const int tid = threadIdx.x;
    const int lane = tid & 31;
    const int warpId = tid >> 5;
    const int sub = lane & 7;
    const int rsel = lane >> 3;

    auto ldh8 = [&](const float* base, int head, __half2* dst, bool neg) {
        const float* p = base + ((size_t)head * BB + b) * 64 + sub * 8;
        float4 f0 = *reinterpret_cast<const float4*>(p);
        float4 f1 = *reinterpret_cast<const float4*>(p + 4);
        dst[0] = __floats2half2_rn(f0.x, f0.y); dst[1] = __floats2half2_rn(f0.z, f0.w);
        dst[2] = __floats2half2_rn(f1.x, f1.y); dst[3] = __floats2half2_rn(f1.z, f1.w);
        if (neg) {
#pragma unroll
            for (int j = 0; j < 4; j++) dst[j] = __hneg2(dst[j]);
        }
    };

    __half2 ne1[4], a1[4], ne3[4], a3[4], ne5[4], a5[4], k0[4], k1[4];
    float kn0 = 0.f, kn1 = 0.f;
    if (ST >= 1) { ldh8(g_ev, 1, ne1, true); ldh8(g_av, 1, a1, false); }
    if (ST >= 2) { ldh8(g_ev, 3, ne3, true); ldh8(g_av, 3, a3, false); }
    if (ST >= 3) { ldh8(g_ev, 5, ne5, true); ldh8(g_av, 5, a5, false); }
    if (NSIM >= 1) { ldh8(g_keyv, SH0, k0, false); kn0 = g_keynorm[SH0 * BB + b]; }
    if (NSIM >= 2) { ldh8(g_keyv, SH0 + 1, k1, false); kn1 = g_keynorm[(SH0 + 1) * BB + b]; }

    float racc[8] = {};
    __half2 racc2[4] = {__floats2half2_rn(0.f, 0.f), __floats2half2_rn(0.f, 0.f),
                        __floats2half2_rn(0.f, 0.f), __floats2half2_rn(0.f, 0.f)};
    const size_t bn = (size_t)b * NN;
    const int rowInBlk = warpId * 4 + rsel;

    uint4 cu = make_uint4(0, 0, 0, 0);
    float4 cf0 = make_float4(0, 0, 0, 0), cf1 = cf0;
    __half cwrh = __float2half_rn(0.f), cw1h = cwrh, cw3h = cwrh, cw5h = cwrh;
    {
        const int n = rowInBlk;
        const size_t hidx = (bn + n) * 64 + sub * 8;
        if (ST == 0) {
            cf0 = __ldcs(reinterpret_cast<const float4*>(mem + hidx));
            cf1 = __ldcs(reinterpret_cast<const float4*>(mem + hidx + 4));
        } else {
            cu = __ldg(reinterpret_cast<const uint4*>(g_memh + hidx));
        }
        if (ST >= 1) { cwrh = s_whr[n]; cw1h = s_wh1[n]; }
        if (ST >= 2) cw3h = s_wh3[n];
        if (ST >= 3) cw5h = s_wh5[n];
    }

#pragma unroll 4
    for (int it = 0; it < 32; it++) {
        const int n = it * 128 + rowInBlk;
        const int n2 = (it < 31) ? (n + 128) : rowInBlk;
        uint4 nu = make_uint4(0, 0, 0, 0);
        float4 nf0 = make_float4(0, 0, 0, 0), nf1 = nf0;
        __half nwrh = __float2half_rn(0.f), nw1h = nwrh, nw3h = nwrh, nw5h = nwrh;
        {
            const size_t hidx2 = (bn + n2) * 64 + sub * 8;
            if (ST == 0) {
                nf0 = __ldcs(reinterpret_cast<const float4*>(mem + hidx2));
                nf1 = __ldcs(reinterpret_cast<const float4*>(mem + hidx2 + 4));
            } else {
                nu = __ldg(reinterpret_cast<const uint4*>(g_memh + hidx2));
            }
            if (ST >= 1) { nwrh = s_whr[n2]; nw1h = s_wh1[n2]; }
            if (ST >= 2) nw3h = s_wh3[n2];
            if (ST >= 3) nw5h = s_wh5[n2];
        }
        __half2 v[4];
        if (ST == 0) {
            v[0] = __floats2half2_rn(cf0.x, cf0.y); v[1] = __floats2half2_rn(cf0.z, cf0.w);
            v[2] = __floats2half2_rn(cf1.x, cf1.y); v[3] = __floats2half2_rn(cf1.z, cf1.w);
            const size_t hidx = (bn + n) * 64 + sub * 8;
            *reinterpret_cast<uint4*>(g_memh + hidx) = *reinterpret_cast<uint4*>(v);
        } else {
            *reinterpret_cast<uint4*>(v) = cu;
        }
        if (ST >= 2) upd8(v, __half2half2(cw1h), ne1, a1);
        if (ST >= 3) upd8(v, __half2half2(cw3h), ne3, a3);
        if (ST == 4) upd8(v, __half2half2(cw5h), ne5, a5);
        if (HAS_READ) {
            __half2 w2r = __half2half2(cwrh);
#pragma unroll
            for (int j = 0; j < 4; j++)
                racc2[j] = __hfma2(w2r, v[j], racc2[j]);
            if ((it & 3) == 3) {
#pragma unroll
                for (int j = 0; j < 4; j++) {
                    float2 f = __half22float2(racc2[j]);
                    racc[2 * j] += f.x; racc[2 * j + 1] += f.y;
                    racc2[j] = __floats2half2_rn(0.f, 0.f);
                }
            }
        }
        if (HAS_POST) {
            __half pwh = (ST == 1) ? cw1h : (ST == 2) ? cw3h : cw5h;
            const __half2* pne = (ST == 1) ? ne1 : (ST == 2) ? ne3 : ne5;
            const __half2* pa  = (ST == 1) ? a1  : (ST == 2) ? a3  : a5;
            upd8(v, __half2half2(pwh), pne, pa);
        }
        if (NSIM >= 1) {
            __half2 ns2 = __floats2half2_rn(0.f, 0.f);
            __half2 d02 = ns2, d12 = ns2;
#pragma unroll
            for (int j = 0; j < 4; j++) {
                ns2 = __hfma2(v[j], v[j], ns2);
                d02 = __hfma2(v[j], k0[j], d02);
                if (NSIM >= 2) d12 = __hfma2(v[j], k1[j], d12);
            }
            float2 nsf = __half22float2(ns2);
            float2 d0f2 = __half22float2(d02);
            float ns = nsf.x + nsf.y;
            float d0 = d0f2.x + d0f2.y;
            if (NSIM >= 2) {
                float2 d1f2 = __half22float2(d12);
                float d1 = d1f2.x + d1f2.y;
                __half2 pd = __floats2half2_rn(d0, d1);
#pragma unroll
                for (int off = 4; off >= 1; off >>= 1)
                    ns += __shfl_xor_sync(0xffffffffu, ns, off);
                pd = shfl8_hadd2(pd);
                if (sub == 0) {
                    float2 dd = __half22float2(pd);
                    float nm = sqrtf(ns);
                    s_simA[n] = dd.x / (nm * kn0 + 1e-8f);
                    s_simB[n] = dd.y / (nm * kn1 + 1e-8f);
                }
            } else {
                __half2 pd = __floats2half2_rn(ns, d0);
                pd = shfl8_hadd2(pd);
                if (sub == 0) {
                    float2 dd = __half22float2(pd);
                    float nm = sqrtf(dd.x);
                    s_simA[n] = dd.y / (nm * kn0 + 1e-8f);
                }
            }
        }
        cu = nu; cf0 = nf0; cf1 = nf1;
        cwrh = nwrh; cw1h = nw1h; cw3h = nw3h; cw5h = nw5h;
    }

    if (HAS_READ) {
        __syncthreads();
#pragma unroll
        for (int j = 0; j < 8; j++) {
            racc[j] += __shfl_down_sync(0xffffffffu, racc[j], 16);
            racc[j] += __shfl_down_sync(0xffffffffu, racc[j], 8);
        }
        if (lane < 8) {
#pragma unroll
            for (int j = 0; j < 8; j++)
                s_wg[warpId * 64 + sub * 8 + j] = racc[j];
        }
        __syncthreads();
        if (tid < 64) {
            float s = 0.f;
#pragma unroll
            for (int w = 0; w < 32; w++) s += s_wg[w * 64 + tid];
            g_hr[(size_t)b * 768 + 512 + RIDX * 64 + tid] = s;
        }
    }
    __syncthreads();

    if (NSIM >= 1) {
        const int hbA = SH0 * BB + b;
        const int hbB = (SH0 + 1) * BB + b;
        __half* destA = s_whr;
        __half* destB = (ST == 0) ? s_wh1 : (ST == 1) ? s_wh3 : s_wh5;
        const float* pwA = prev_weights + (size_t)hbA * NN;
        const float* pwB = prev_weights + (size_t)hbB * NN;
        const float betaA = g_beta[hbA], ggA = g_gv[hbA], gamA = g_gamma[hbA];
        const float sA0 = g_sv[(size_t)hbA * 3 + 0];
        const float sA1 = g_sv[(size_t)hbA * 3 + 1];
        const float sA2 = g_sv[(size_t)hbA * 3 + 2];
        float betaB = 0.f, ggB = 0.f, gamB = 1.f, sB0 = 0.f, sB1 = 0.f, sB2 = 0.f;
        if (NSIM >= 2) {
            betaB = g_beta[hbB]; ggB = g_gv[hbB]; gamB = g_gamma[hbB];
            sB0 = g_sv[(size_t)hbB * 3 + 0];
            sB1 = g_sv[(size_t)hbB * 3 + 1];
            sB2 = g_sv[(size_t)hbB * 3 + 2];
        }

        float exA[4], exB[4];
        float2 se = make_float2(0.f, 0.f);
#pragma unroll
        for (int j = 0; j < 4; j++) {
            int n = tid + 1024 * j;
            exA[j] = __expf(betaA * s_simA[n]); se.x += exA[j];
            if (NSIM >= 2) { exB[j] = __expf(betaB * s_simB[n]); se.y += exB[j]; }
        }
        se = blk_reduce_f2(se, s_red);
        const float invA = 1.f / se.x;
        const float invB = (NSIM >= 2) ? 1.f / se.y : 0.f;
#pragma unroll
        for (int j = 0; j < 4; j++) {
            int n = tid + 1024 * j;
            s_simA[n] = ggA * (exA[j] * invA) + (1.f - ggA) * pwA[n];
            if (NSIM >= 2) s_simB[n] = ggB * (exB[j] * invB) + (1.f - ggB) * pwB[n];
        }
        __syncthreads();
        float pA[4], pB[4];
        float2 sp = make_float2(0.f, 0.f);
#pragma unroll
        for (int j = 0; j < 4; j++) {
            int n = tid + 1024 * j;
            int np = (n + 1) & (NN - 1), nm = (n - 1) & (NN - 1);
            float wsA = sA0 * s_simA[np] + sA1 * s_simA[n] + sA2 * s_simA[nm];
            pA[j] = __powf(wsA, gamA); sp.x += pA[j];
            if (NSIM >= 2) {
                float wsB = sB0 * s_simB[np] + sB1 * s_simB[n] + sB2 * s_simB[nm];
                pB[j] = __powf(wsB, gamB); sp.y += pB[j];
            }
        }
        sp = blk_reduce_f2(sp, s_red);
        const float invpA = 1.f / (sp.x + 1e-8f);
        const float invpB = (NSIM >= 2) ? 1.f / (sp.y + 1e-8f) : 0.f;
#pragma unroll
        for (int j = 0; j < 4; j++) {
            int n = tid + 1024 * j;
            destA[n] = __float2half_rn(pA[j] * invpA);
            if (NSIM >= 2) destB[n] = __float2half_rn(pB[j] * invpB);
        }
        __syncthreads();
    }
}

__global__ __launch_bounds__(1024, 1) void mega_pass(
    const float* __restrict__ mem, const float* __restrict__ prev_weights,
    const float* __restrict__ bk, const float* __restrict__ be,
    const float* __restrict__ ba, const float* __restrict__ bs,
    const float* __restrict__ bbeta, const float* __restrict__ bg,
    const float* __restrict__ bgam)
{
    extern __shared__ float smem[];
    float* s_simA = smem;
    float* s_simB = smem + 4096;
    float* s_wg   = smem + 8192;
    float2* s_red = reinterpret_cast<float2*>(smem + 10240);
    __half* s_whr = reinterpret_cast<__half*>(smem + 10304);
    __half* s_wh1 = s_whr + 4096;
    __half* s_wh3 = s_wh1 + 4096;
    __half* s_wh5 = s_wh3 + 4096;
    const int b = blockIdx.x;

    // prologue: per-batch head params (formerly param_act_kernel)
    param_act_body(b, s_wg, s_wg + 128, bk, be, ba, bs, bbeta, bg, bgam);

    pass_body<0>(mem, prev_weights, b, s_simA, s_simB, s_wg, s_red, s_whr, s_wh1, s_wh3, s_wh5);
    __syncthreads();
    pass_body<1>(mem, prev_weights, b, s_simA, s_simB, s_wg, s_red, s_whr, s_wh1, s_wh3, s_wh5);
    __syncthreads();
    pass_body<2>(mem, prev_weights, b, s_simA, s_simB, s_wg, s_red, s_whr, s_wh1, s_wh3, s_wh5);
    __syncthreads();
    pass_body<3>(mem, prev_weights, b, s_simA, s_simB, s_wg, s_red, s_whr, s_wh1, s_wh3, s_wh5);
    __syncthreads();
    pass_body<4>(mem, prev_weights, b, s_simA, s_simB, s_wg, s_red, s_whr, s_wh1, s_wh3, s_wh5);
}

// ---------------- output epilogue ----------------
__global__ void out_act_kernel(const float* __restrict__ b_out, float* __restrict__ out) {
    int b = blockIdx.x, j = threadIdx.x;  // 256 threads
    float v = b_out[j];
#pragma unroll
    for (int sl = 0; sl < 6; sl++)
        v += g_op[((size_t)sl * BB + b) * 256 + j];
    out[(size_t)b * 256 + j] = 1.f / (1.f + expf(-v));
}

// ---------------- launch ----------------
extern "C" void kernel_launch(void* const* d_in, const int* in_sizes, int n_in,
                              void* d_out, int out_size) {
    const float* in_data      = (const float*)d_in[0];
    const float* memory       = (const float*)d_in[1];
    const float* h_prev       = (const float*)d_in[2];
    const float* c_prev       = (const float*)d_in[3];
    const float* prev_reads   = (const float*)d_in[4];
    const float* prev_weights = (const float*)d_in[5];
    const float* W_ih  = (const float*)d_in[6];
    const float* b_ih  = (const float*)d_in[7];
    const float* W_hh  = (const float*)d_in[8];
    const float* b_hh  = (const float*)d_in[9];
    const float* W_out = (const float*)d_in[10];
    const float* b_out = (const float*)d_in[11];
    const float* Wk    = (const float*)d_in[12];
    const float* bk    = (const float*)d_in[13];
    const float* Wbeta = (const float*)d_in[14];
    const float* bbeta = (const float*)d_in[15];
    const float* Wg    = (const float*)d_in[16];
    const float* bg    = (const float*)d_in[17];
    const float* Ws    = (const float*)d_in[18];
    const float* bs    = (const float*)d_in[19];
    const float* Wgam  = (const float*)d_in[20];
    const float* bgam  = (const float*)d_in[21];
    const float* We    = (const float*)d_in[22];
    const float* be    = (const float*)d_in[23];
    const float* Wa    = (const float*)d_in[24];
    const float* ba    = (const float*)d_in[25];
    float* out = (float*)d_out;

    float* gp; cudaGetSymbolAddress((void**)&gp, g_gp);
    float* pp; cudaGetSymbolAddress((void**)&pp, g_pp);
    float* op; cudaGetSymbolAddress((void**)&op, g_op);
    float* ghr; cudaGetSymbolAddress((void**)&ghr, g_hr);

    cudaFuncSetAttribute(mega_pass, cudaFuncAttributeMaxDynamicSharedMemorySize, MEGA_SMEM);

    // 1. LSTM gates (inline x-gather; both GEMMs, 8 split-K slots) + activation
    gemm_gates<<<dim3(32, 2, 8), 256>>>(in_data, prev_reads, h_prev, W_ih, W_hh, gp);
    lstm_act_kernel<<<(BB * 128 + 255) / 256, 256>>>(b_ih, b_hh, c_prev);

    // 2. head-param GEMM (inline W gather, 8 split-K slots, 400 blocks)
    gemm_param<<<dim3(25, 2, 8), 256>>>(Wk, We, Wa, Ws, Wbeta, Wg, Wgam, pp);

    // 3. all 5 memory passes + param-act prologue in ONE kernel
    mega_pass<<<BB, 1024, MEGA_SMEM>>>(memory, prev_weights,
                                       bk, be, ba, bs, bbeta, bg, bgam);

    // 4. output layer
    gemm_tn<<<dim3(4, 2, 6), 256>>>(ghr, W_out, op, 256, 768, 128, 0);
    out_act_kernel<<<BB, 256>>>(b_out, out);
}